// round 1
// baseline (speedup 1.0000x reference)
#include <cuda_runtime.h>

#define BB 2
#define SS 4096
#define DD 128
#define HH 4
#define DH 32
#define BHT (BB*HH)
#define KSPLIT 4
#define QSCALE 0.17677669529663687f   // 1/sqrt(32)

// ---------------- scratch (device globals; no allocations) ----------------
__device__ __align__(16) float g_q[BHT*SS*DH];
__device__ __align__(16) float g_k[BHT*SS*DH];
__device__ __align__(16) float g_v[BHT*SS*DH];
__device__ __align__(16) float g_vsum[BHT*DH];
__device__ __align__(16) float g_lpart[BHT*SS*KSPLIT];
__device__ __align__(16) float g_opart[BHT*SS*KSPLIT*DH];
__device__ __align__(16) float g_z[BB*SS*DD];

// ---------------- 1) QKV projection -----------------
// grid: (B*S/16) blocks, 384 threads. Thread t: matrix = t/128 (0=Q,1=K,2=V),
// output o = t%128 = h*32+d. 16 x-rows per block staged in smem.
__global__ void __launch_bounds__(384) proj_kernel(
    const float* __restrict__ x,
    const float* __restrict__ Wk,
    const float* __restrict__ Wq,
    const float* __restrict__ Wv)
{
    const int R = 16;
    __shared__ __align__(16) float xs[R][DD];
    int rowbase = blockIdx.x * R;
    int tid = threadIdx.x;
    for (int i = tid; i < R * DD; i += 384)
        xs[i / DD][i % DD] = x[rowbase * DD + i];
    __syncthreads();

    int mat = tid >> 7;
    int o = tid & 127;
    const float* W = (mat == 0) ? Wq : (mat == 1) ? Wk : Wv;
    float* G = (mat == 0) ? g_q : (mat == 1) ? g_k : g_v;
    const float4* Wrow = (const float4*)(W + o * DD);

    float acc[R];
#pragma unroll
    for (int r = 0; r < R; r++) acc[r] = 0.f;

#pragma unroll 8
    for (int jc = 0; jc < DD / 4; jc++) {
        float4 w = Wrow[jc];
#pragma unroll
        for (int r = 0; r < R; r++) {
            float4 xv = *(const float4*)(&xs[r][jc * 4]);
            acc[r] = fmaf(w.x, xv.x, acc[r]);
            acc[r] = fmaf(w.y, xv.y, acc[r]);
            acc[r] = fmaf(w.z, xv.z, acc[r]);
            acc[r] = fmaf(w.w, xv.w, acc[r]);
        }
    }
    int h = o >> 5, d = o & 31;
#pragma unroll
    for (int r = 0; r < R; r++) {
        int row = rowbase + r;
        int b = row / SS, p = row % SS;
        G[((b * HH + h) * SS + p) * DH + d] = acc[r];
    }
}

// ---------------- 2) V column-sum per (b,h) -----------------
__global__ void __launch_bounds__(256) vsum_kernel()
{
    int bh = blockIdx.x;
    int d = threadIdx.x & 31;
    int c = threadIdx.x >> 5;   // 0..7
    float s = 0.f;
    for (int p = c; p < SS; p += 8)
        s += g_v[(bh * SS + p) * DH + d];
    __shared__ float red[8][32];
    red[c][d] = s;
    __syncthreads();
    if (c == 0) {
        float t = 0.f;
#pragma unroll
        for (int i = 0; i < 8; i++) t += red[i][d];
        g_vsum[bh * DH + d] = t;
    }
}

// ---------------- 3) attention core (no-max softmax, key-split) ----------
// grid: (BH, S/128, KSPLIT), 128 threads: one query per thread.
__global__ void __launch_bounds__(128) attn_kernel()
{
    int bh = blockIdx.x;
    int qt = blockIdx.y;
    int ks = blockIdx.z;
    int tid = threadIdx.x;
    int q = qt * 128 + tid;

    __shared__ __align__(16) float sK[128 * DH];
    __shared__ __align__(16) float sV[128 * DH];

    float4 qv[8];
    const float4* qp = (const float4*)(g_q + (bh * SS + q) * DH);
#pragma unroll
    for (int i = 0; i < 8; i++) {
        float4 t = qp[i];
        t.x *= QSCALE; t.y *= QSCALE; t.z *= QSCALE; t.w *= QSCALE;
        qv[i] = t;
    }
    float4 ov[8];
#pragma unroll
    for (int i = 0; i < 8; i++) ov[i] = make_float4(0.f, 0.f, 0.f, 0.f);
    float l = 0.f;

    const int kchunk = SS / KSPLIT;        // 1024 keys
    int k0base = ks * kchunk;

    for (int t = 0; t < kchunk / 128; t++) {
        int k0 = k0base + t * 128;
        const float4* gK = (const float4*)(g_k + (bh * SS + k0) * DH);
        const float4* gV = (const float4*)(g_v + (bh * SS + k0) * DH);
        __syncthreads();
        float4* sK4 = (float4*)sK;
        float4* sV4 = (float4*)sV;
#pragma unroll
        for (int i = 0; i < 8; i++) {
            sK4[i * 128 + tid] = gK[i * 128 + tid];
            sV4[i * 128 + tid] = gV[i * 128 + tid];
        }
        __syncthreads();

#pragma unroll 2
        for (int j = 0; j < 128; j++) {
            const float4* kr = (const float4*)(sK + j * DH);
            float s0 = 0.f, s1 = 0.f, s2 = 0.f, s3 = 0.f;
#pragma unroll
            for (int i = 0; i < 8; i++) {
                float4 kk = kr[i];
                s0 = fmaf(qv[i].x, kk.x, s0);
                s1 = fmaf(qv[i].y, kk.y, s1);
                s2 = fmaf(qv[i].z, kk.z, s2);
                s3 = fmaf(qv[i].w, kk.w, s3);
            }
            float s = (s0 + s1) + (s2 + s3);
            float p = __expf(s);
            l += p;
            const float4* vr = (const float4*)(sV + j * DH);
#pragma unroll
            for (int i = 0; i < 8; i++) {
                float4 vv = vr[i];
                ov[i].x = fmaf(p, vv.x, ov[i].x);
                ov[i].y = fmaf(p, vv.y, ov[i].y);
                ov[i].z = fmaf(p, vv.z, ov[i].z);
                ov[i].w = fmaf(p, vv.w, ov[i].w);
            }
        }
    }

    g_lpart[(bh * SS + q) * KSPLIT + ks] = l;
    float4* op = (float4*)(g_opart + ((size_t)(bh * SS + q) * KSPLIT + ks) * DH);
#pragma unroll
    for (int i = 0; i < 8; i++) op[i] = ov[i];
}

// ---------------- 4) combine splits + blend + head interleave ------------
__global__ void __launch_bounds__(256) combine_kernel()
{
    int gid = blockIdx.x * 256 + threadIdx.x;
    int q = gid >> 5;            // 0..BH*S-1
    int d = gid & 31;
    int bh = q >> 12;            // /4096
    int p = q & 4095;
    float l = 0.f, o = 0.f;
#pragma unroll
    for (int k = 0; k < KSPLIT; k++) {
        l += g_lpart[q * KSPLIT + k];
        o += g_opart[((size_t)q * KSPLIT + k) * DH + d];
    }
    float z = 0.5f * (o / l) + 0.5f * g_vsum[bh * DH + d];
    int b = bh >> 2, h = bh & 3;
    g_z[(b * SS + p) * DD + h * DH + d] = z;
}

// ---------------- 5) output projection: out = z @ W_O^T -------------------
__global__ void __launch_bounds__(128) out_kernel(
    const float* __restrict__ Wo, float* __restrict__ out)
{
    const int R = 16;
    __shared__ __align__(16) float zs[R][DD];
    int rowbase = blockIdx.x * R;
    int tid = threadIdx.x;
    for (int i = tid; i < R * DD; i += 128)
        zs[i / DD][i % DD] = g_z[rowbase * DD + i];
    __syncthreads();

    const float4* Wr = (const float4*)(Wo + tid * DD);
    float acc[R];
#pragma unroll
    for (int r = 0; r < R; r++) acc[r] = 0.f;
#pragma unroll 8
    for (int jc = 0; jc < DD / 4; jc++) {
        float4 w = Wr[jc];
#pragma unroll
        for (int r = 0; r < R; r++) {
            float4 zv = *(const float4*)(&zs[r][jc * 4]);
            acc[r] = fmaf(w.x, zv.x, acc[r]);
            acc[r] = fmaf(w.y, zv.y, acc[r]);
            acc[r] = fmaf(w.z, zv.z, acc[r]);
            acc[r] = fmaf(w.w, zv.w, acc[r]);
        }
    }
#pragma unroll
    for (int r = 0; r < R; r++)
        out[(rowbase + r) * DD + tid] = acc[r];
}

// ---------------- launch ----------------
extern "C" void kernel_launch(void* const* d_in, const int* in_sizes, int n_in,
                              void* d_out, int out_size)
{
    const float* x  = (const float*)d_in[0];
    const float* Wk = (const float*)d_in[1];
    const float* Wq = (const float*)d_in[2];
    const float* Wv = (const float*)d_in[3];
    const float* Wo = (const float*)d_in[4];
    float* out = (float*)d_out;

    proj_kernel<<<(BB * SS) / 16, 384>>>(x, Wk, Wq, Wv);
    vsum_kernel<<<BHT, 256>>>();
    {
        dim3 grid(BHT, SS / 128, KSPLIT);
        attn_kernel<<<grid, 128>>>();
    }
    combine_kernel<<<(BHT * SS * DH) / 256, 256>>>();
    out_kernel<<<(BB * SS) / 16, 128>>>(Wo, out);
}

// round 2
// speedup vs baseline: 1.4276x; 1.4276x over previous
#include <cuda_runtime.h>

#define BB 2
#define SS 4096
#define DD 128
#define HH 4
#define DH 32
#define BHT (BB*HH)
#define KSPLIT 8
#define QSCALE 0.17677669529663687f   // 1/sqrt(32)

typedef unsigned long long u64;

// packed f32x2 helpers (sm_103a FFMA2 path — PTX-only)
#define FMA2(d,a,b,c) asm("fma.rn.f32x2 %0,%1,%2,%3;" : "=l"(d) : "l"(a), "l"(b), "l"(c))
#define MUL2(d,a,b)   asm("mul.rn.f32x2 %0,%1,%2;"    : "=l"(d) : "l"(a), "l"(b))
#define PACK2(v,lo,hi)   asm("mov.b64 %0, {%1,%2};" : "=l"(v) : "f"(lo), "f"(hi))
#define UNPACK2(lo,hi,v) asm("mov.b64 {%0,%1}, %2;" : "=f"(lo), "=f"(hi) : "l"(v))

// ---------------- scratch (device globals; no allocations) ----------------
__device__ __align__(16) float g_q[BHT*SS*DH];
__device__ __align__(16) float g_k[BHT*SS*DH];
__device__ __align__(16) float g_v[BHT*SS*DH];
__device__ __align__(16) float g_vsum[BHT*DH];
__device__ __align__(16) float g_lpart[BHT*SS*KSPLIT];
__device__ __align__(16) float g_opart[(size_t)BHT*SS*KSPLIT*DH];
__device__ __align__(16) float g_z[BB*SS*DD];

// ---------------- 1) QKV projection -----------------
__global__ void __launch_bounds__(384) proj_kernel(
    const float* __restrict__ x,
    const float* __restrict__ Wk,
    const float* __restrict__ Wq,
    const float* __restrict__ Wv)
{
    const int R = 16;
    __shared__ __align__(16) float xs[R][DD];
    int rowbase = blockIdx.x * R;
    int tid = threadIdx.x;
    for (int i = tid; i < R * DD; i += 384)
        xs[i / DD][i % DD] = x[rowbase * DD + i];
    __syncthreads();

    int mat = tid >> 7;
    int o = tid & 127;
    const float* W = (mat == 0) ? Wq : (mat == 1) ? Wk : Wv;
    float* G = (mat == 0) ? g_q : (mat == 1) ? g_k : g_v;
    const float4* Wrow = (const float4*)(W + o * DD);

    float acc[R];
#pragma unroll
    for (int r = 0; r < R; r++) acc[r] = 0.f;

#pragma unroll 8
    for (int jc = 0; jc < DD / 4; jc++) {
        float4 w = Wrow[jc];
#pragma unroll
        for (int r = 0; r < R; r++) {
            float4 xv = *(const float4*)(&xs[r][jc * 4]);
            acc[r] = fmaf(w.x, xv.x, acc[r]);
            acc[r] = fmaf(w.y, xv.y, acc[r]);
            acc[r] = fmaf(w.z, xv.z, acc[r]);
            acc[r] = fmaf(w.w, xv.w, acc[r]);
        }
    }
    int h = o >> 5, d = o & 31;
#pragma unroll
    for (int r = 0; r < R; r++) {
        int row = rowbase + r;
        int b = row / SS, p = row % SS;
        G[((b * HH + h) * SS + p) * DH + d] = acc[r];
    }
}

// ---------------- 2) V column-sum per (b,h) -----------------
__global__ void __launch_bounds__(256) vsum_kernel()
{
    int bh = blockIdx.x;
    int d = threadIdx.x & 31;
    int c = threadIdx.x >> 5;   // 0..7
    float s = 0.f;
    for (int p = c; p < SS; p += 8)
        s += g_v[(bh * SS + p) * DH + d];
    __shared__ float red[8][32];
    red[c][d] = s;
    __syncthreads();
    if (c == 0) {
        float t = 0.f;
#pragma unroll
        for (int i = 0; i < 8; i++) t += red[i][d];
        g_vsum[bh * DH + d] = t;
    }
}

// ---------------- 3) attention core: FFMA2, 2 queries/thread --------------
// grid: (BH, S/256, KSPLIT), 128 threads. Thread handles queries q0, q0+128.
__global__ void __launch_bounds__(128, 2) attn_kernel()
{
    int bh = blockIdx.x;
    int qt = blockIdx.y;
    int ks = blockIdx.z;
    int tid = threadIdx.x;
    int q0 = qt * 256 + tid;

    __shared__ __align__(16) ulonglong2 sK[128 * 8];
    __shared__ __align__(16) ulonglong2 sV[128 * 8];

    u64 qa[16], qb[16], oa[16], ob[16];
    u64 qs; PACK2(qs, QSCALE, QSCALE);
    const ulonglong2* qpa = (const ulonglong2*)(g_q + (bh * SS + q0) * DH);
    const ulonglong2* qpb = (const ulonglong2*)(g_q + (bh * SS + q0 + 128) * DH);
#pragma unroll
    for (int i = 0; i < 8; i++) {
        ulonglong2 t = qpa[i];
        MUL2(qa[2*i],   t.x, qs);
        MUL2(qa[2*i+1], t.y, qs);
        ulonglong2 u = qpb[i];
        MUL2(qb[2*i],   u.x, qs);
        MUL2(qb[2*i+1], u.y, qs);
        oa[2*i] = 0ull; oa[2*i+1] = 0ull;
        ob[2*i] = 0ull; ob[2*i+1] = 0ull;
    }
    float lA = 0.f, lB = 0.f;

    const int kchunk = SS / KSPLIT;           // 512 keys
    int k0base = ks * kchunk;

    for (int t = 0; t < kchunk / 128; t++) {
        int k0 = k0base + t * 128;
        const ulonglong2* gK = (const ulonglong2*)(g_k + (bh * SS + k0) * DH);
        const ulonglong2* gV = (const ulonglong2*)(g_v + (bh * SS + k0) * DH);
        __syncthreads();
#pragma unroll
        for (int i = 0; i < 8; i++) {
            sK[i * 128 + tid] = gK[i * 128 + tid];
            sV[i * 128 + tid] = gV[i * 128 + tid];
        }
        __syncthreads();

#pragma unroll 2
        for (int j = 0; j < 128; j++) {
            u64 a0 = 0, a1 = 0, a2 = 0, a3 = 0;
            u64 b0 = 0, b1 = 0, b2 = 0, b3 = 0;
#pragma unroll
            for (int i = 0; i < 8; i += 2) {
                ulonglong2 k1 = sK[j * 8 + i];
                FMA2(a0, qa[2*i],   k1.x, a0);
                FMA2(a1, qa[2*i+1], k1.y, a1);
                FMA2(b0, qb[2*i],   k1.x, b0);
                FMA2(b1, qb[2*i+1], k1.y, b1);
                ulonglong2 k2 = sK[j * 8 + i + 1];
                FMA2(a2, qa[2*i+2], k2.x, a2);
                FMA2(a3, qa[2*i+3], k2.y, a3);
                FMA2(b2, qb[2*i+2], k2.x, b2);
                FMA2(b3, qb[2*i+3], k2.y, b3);
            }
            float x0,x1,x2,x3,x4,x5,x6,x7;
            UNPACK2(x0,x1,a0); UNPACK2(x2,x3,a1);
            UNPACK2(x4,x5,a2); UNPACK2(x6,x7,a3);
            float sA = ((x0+x1)+(x2+x3)) + ((x4+x5)+(x6+x7));
            UNPACK2(x0,x1,b0); UNPACK2(x2,x3,b1);
            UNPACK2(x4,x5,b2); UNPACK2(x6,x7,b3);
            float sB = ((x0+x1)+(x2+x3)) + ((x4+x5)+(x6+x7));

            float pA = __expf(sA); lA += pA;
            float pB = __expf(sB); lB += pB;
            u64 pA2, pB2;
            PACK2(pA2, pA, pA);
            PACK2(pB2, pB, pB);
#pragma unroll
            for (int i = 0; i < 8; i++) {
                ulonglong2 vv = sV[j * 8 + i];
                FMA2(oa[2*i],   pA2, vv.x, oa[2*i]);
                FMA2(oa[2*i+1], pA2, vv.y, oa[2*i+1]);
                FMA2(ob[2*i],   pB2, vv.x, ob[2*i]);
                FMA2(ob[2*i+1], pB2, vv.y, ob[2*i+1]);
            }
        }
    }

    g_lpart[(bh * SS + q0) * KSPLIT + ks]       = lA;
    g_lpart[(bh * SS + q0 + 128) * KSPLIT + ks] = lB;
    u64* opa = (u64*)(g_opart + ((size_t)(bh * SS + q0) * KSPLIT + ks) * DH);
    u64* opb = (u64*)(g_opart + ((size_t)(bh * SS + q0 + 128) * KSPLIT + ks) * DH);
#pragma unroll
    for (int i = 0; i < 16; i++) { opa[i] = oa[i]; opb[i] = ob[i]; }
}

// ---------------- 4) combine splits + blend + head interleave ------------
// one thread per (q, 4-wide d chunk): 8 threads per q
__global__ void __launch_bounds__(256) combine_kernel()
{
    int gid = blockIdx.x * 256 + threadIdx.x;
    int q  = gid >> 3;           // 0..BH*S-1
    int dq = gid & 7;            // float4 index within DH=32
    int bh = q >> 12;
    int p  = q & 4095;

    float l = 0.f;
#pragma unroll
    for (int k = 0; k < KSPLIT; k++) l += g_lpart[q * KSPLIT + k];

    float4 o = make_float4(0.f, 0.f, 0.f, 0.f);
#pragma unroll
    for (int k = 0; k < KSPLIT; k++) {
        float4 t = ((const float4*)(g_opart + ((size_t)q * KSPLIT + k) * DH))[dq];
        o.x += t.x; o.y += t.y; o.z += t.z; o.w += t.w;
    }
    float inv = 0.5f / l;
    float4 vs = ((const float4*)(g_vsum + bh * DH))[dq];
    float4 z;
    z.x = fmaf(o.x, inv, 0.5f * vs.x);
    z.y = fmaf(o.y, inv, 0.5f * vs.y);
    z.z = fmaf(o.z, inv, 0.5f * vs.z);
    z.w = fmaf(o.w, inv, 0.5f * vs.w);
    int b = bh >> 2, h = bh & 3;
    ((float4*)(g_z + (b * SS + p) * DD + h * DH))[dq] = z;
}

// ---------------- 5) output projection: out = z @ W_O^T -------------------
__global__ void __launch_bounds__(128) out_kernel(
    const float* __restrict__ Wo, float* __restrict__ out)
{
    const int R = 16;
    __shared__ __align__(16) float zs[R][DD];
    int rowbase = blockIdx.x * R;
    int tid = threadIdx.x;
    for (int i = tid; i < R * DD; i += 128)
        zs[i / DD][i % DD] = g_z[rowbase * DD + i];
    __syncthreads();

    const float4* Wr = (const float4*)(Wo + tid * DD);
    float acc[R];
#pragma unroll
    for (int r = 0; r < R; r++) acc[r] = 0.f;
#pragma unroll 8
    for (int jc = 0; jc < DD / 4; jc++) {
        float4 w = Wr[jc];
#pragma unroll
        for (int r = 0; r < R; r++) {
            float4 zv = *(const float4*)(&zs[r][jc * 4]);
            acc[r] = fmaf(w.x, zv.x, acc[r]);
            acc[r] = fmaf(w.y, zv.y, acc[r]);
            acc[r] = fmaf(w.z, zv.z, acc[r]);
            acc[r] = fmaf(w.w, zv.w, acc[r]);
        }
    }
#pragma unroll
    for (int r = 0; r < R; r++)
        out[(rowbase + r) * DD + tid] = acc[r];
}

// ---------------- launch ----------------
extern "C" void kernel_launch(void* const* d_in, const int* in_sizes, int n_in,
                              void* d_out, int out_size)
{
    const float* x  = (const float*)d_in[0];
    const float* Wk = (const float*)d_in[1];
    const float* Wq = (const float*)d_in[2];
    const float* Wv = (const float*)d_in[3];
    const float* Wo = (const float*)d_in[4];
    float* out = (float*)d_out;

    proj_kernel<<<(BB * SS) / 16, 384>>>(x, Wk, Wq, Wv);
    vsum_kernel<<<BHT, 256>>>();
    {
        dim3 grid(BHT, SS / 256, KSPLIT);
        attn_kernel<<<grid, 128>>>();
    }
    combine_kernel<<<(BHT * SS * 8) / 256, 256>>>();
    out_kernel<<<(BB * SS) / 16, 128>>>(Wo, out);
}

// round 3
// speedup vs baseline: 4.5368x; 3.1780x over previous
#include <cuda_runtime.h>
#include <cuda_bf16.h>

#define BB 2
#define SS 4096
#define DD 128
#define HH 4
#define DH 32
#define BHT (BB*HH)
#define KS 8
#define QSCALE 0.17677669529663687f   // 1/sqrt(32)
#define LOG2E  1.4426950408889634f

typedef unsigned int u32;

// ---------------- scratch (device globals; no allocations) ----------------
__device__ __align__(16) __nv_bfloat16 g_qb[(size_t)BHT*SS*DH];
__device__ __align__(16) __nv_bfloat16 g_kb[(size_t)BHT*SS*DH];
__device__ __align__(16) __nv_bfloat16 g_vb[(size_t)BHT*SS*DH];
__device__ __align__(16) float g_xpart[BB*8][DD];
__device__ __align__(16) float g_vsum[BHT*DH];
__device__ __align__(16) float g_lpart[(size_t)BHT*SS*KS];
__device__ __align__(16) float g_opart[(size_t)BHT*SS*KS*DH];
__device__ __align__(16) float g_z[BB*SS*DD];

// ---------------- asm helpers ----------------
__device__ __forceinline__ u32 smaddr(const void* p) {
    u32 a;
    asm("{.reg .u64 t; cvta.to.shared.u64 t, %1; cvt.u32.u64 %0, t;}" : "=r"(a) : "l"(p));
    return a;
}
#define LDSM4(r0,r1,r2,r3,a) \
    asm volatile("ldmatrix.sync.aligned.m8n8.x4.shared.b16 {%0,%1,%2,%3},[%4];" \
        : "=r"(r0),"=r"(r1),"=r"(r2),"=r"(r3) : "r"(a))
#define LDSM4T(r0,r1,r2,r3,a) \
    asm volatile("ldmatrix.sync.aligned.m8n8.x4.trans.shared.b16 {%0,%1,%2,%3},[%4];" \
        : "=r"(r0),"=r"(r1),"=r"(r2),"=r"(r3) : "r"(a))
#define MMA(c0,c1,c2,c3,a0,a1,a2,a3,b0,b1) \
    asm volatile("mma.sync.aligned.m16n8k16.row.col.f32.bf16.bf16.f32 " \
        "{%0,%1,%2,%3},{%4,%5,%6,%7},{%8,%9},{%0,%1,%2,%3};" \
        : "+f"(c0),"+f"(c1),"+f"(c2),"+f"(c3) \
        : "r"(a0),"r"(a1),"r"(a2),"r"(a3),"r"(b0),"r"(b1))
#define EX2(d,s) asm("ex2.approx.ftz.f32 %0,%1;" : "=f"(d) : "f"(s))
#define CVTB2(d,hi,lo) asm("cvt.rn.bf16x2.f32 %0,%1,%2;" : "=r"(d) : "f"(hi),"f"(lo))

// swizzled element offset within a [rows x 32] bf16 tile (16B-chunk XOR swizzle)
__device__ __forceinline__ int swoff(int row, int chunk) {
    return row * 32 + (((chunk) ^ ((row >> 1) & 3)) << 3);
}

// ---------------- 1) QKV projection (fp32 math -> bf16 out) ---------------
__global__ void __launch_bounds__(384) proj_kernel(
    const float* __restrict__ x,
    const float* __restrict__ Wk,
    const float* __restrict__ Wq,
    const float* __restrict__ Wv)
{
    const int R = 16;
    __shared__ __align__(16) float xs[R][DD];
    int rowbase = blockIdx.x * R;
    int tid = threadIdx.x;
    for (int i = tid; i < R * DD; i += 384)
        xs[i / DD][i % DD] = x[rowbase * DD + i];
    __syncthreads();

    int mat = tid >> 7;
    int o = tid & 127;
    const float* W = (mat == 0) ? Wq : (mat == 1) ? Wk : Wv;
    __nv_bfloat16* G = (mat == 0) ? g_qb : (mat == 1) ? g_kb : g_vb;
    float scale = (mat == 0) ? (QSCALE * LOG2E) : 1.0f;
    const float4* Wrow = (const float4*)(W + o * DD);

    float acc[R];
#pragma unroll
    for (int r = 0; r < R; r++) acc[r] = 0.f;

#pragma unroll 8
    for (int jc = 0; jc < DD / 4; jc++) {
        float4 w = Wrow[jc];
#pragma unroll
        for (int r = 0; r < R; r++) {
            float4 xv = *(const float4*)(&xs[r][jc * 4]);
            acc[r] = fmaf(w.x, xv.x, acc[r]);
            acc[r] = fmaf(w.y, xv.y, acc[r]);
            acc[r] = fmaf(w.z, xv.z, acc[r]);
            acc[r] = fmaf(w.w, xv.w, acc[r]);
        }
    }
    int h = o >> 5, d = o & 31;
#pragma unroll
    for (int r = 0; r < R; r++) {
        int row = rowbase + r;
        int b = row / SS, p = row % SS;
        G[((size_t)(b * HH + h) * SS + p) * DH + d] = __float2bfloat16(acc[r] * scale);
    }
}

// ---------------- 2a) x column-sum partials (fp32 exact path) -------------
__global__ void __launch_bounds__(512) xsum_kernel(const float* __restrict__ x)
{
    int blk = blockIdx.x;            // 0..15 : b*8 + part
    int d = threadIdx.x & 127;
    int c = threadIdx.x >> 7;        // 0..3
    int b = blk >> 3, part = blk & 7;
    const float* base = x + ((size_t)b * SS + part * 512) * DD;
    float s = 0.f;
    for (int j = c; j < 512; j += 4)
        s += base[j * DD + d];
    __shared__ float red[4][DD];
    red[c][d] = s;
    __syncthreads();
    if (c == 0)
        g_xpart[blk][d] = red[0][d] + red[1][d] + red[2][d] + red[3][d];
}

// ---------------- 2b) vsum = W_V . xsum (fp32) -----------------------------
__global__ void __launch_bounds__(128) vsumw_kernel(const float* __restrict__ Wv)
{
    int bh = blockIdx.x;
    int b = bh >> 2, h = bh & 3;
    __shared__ float xs[DD];
    int tid = threadIdx.x;
    if (tid < DD) {
        float s = 0.f;
#pragma unroll
        for (int p = 0; p < 8; p++) s += g_xpart[b * 8 + p][tid];
        xs[tid] = s;
    }
    __syncthreads();
    if (tid < DH) {
        const float* Wr = Wv + (size_t)(h * DH + tid) * DD;
        float s = 0.f;
#pragma unroll 4
        for (int j = 0; j < DD; j++) s = fmaf(Wr[j], xs[j], s);
        g_vsum[bh * DH + tid] = s;
    }
}

// ---------------- 3) attention core: bf16 mma.sync ------------------------
// grid (BHT, SS/128, KS), 256 threads (8 warps x 16 queries)
__global__ void __launch_bounds__(256, 2) attn_kernel()
{
    int bh = blockIdx.x;
    int qt = blockIdx.y;
    int ks = blockIdx.z;
    int tid = threadIdx.x;
    int w = tid >> 5, lane = tid & 31;
    int lrow = lane & 15, lchunk = lane >> 4;   // ldmatrix address pattern

    __shared__ __align__(16) __nv_bfloat16 sK[128 * 32];
    __shared__ __align__(16) __nv_bfloat16 sV[128 * 32];

    // ---- stage Q tile (128 q x 32 d) into sK, build A fragments ----
    {
        const uint4* gQ = (const uint4*)(g_qb + ((size_t)bh * SS + qt * 128) * DH);
        for (int i = tid; i < 512; i += 256) {
            int row = i >> 2, c = i & 3;
            *(uint4*)(sK + swoff(row, c)) = gQ[i];
        }
    }
    __syncthreads();
    u32 qf[8];
    {
        int row = w * 16 + lrow;
        u32 a0 = smaddr(sK + swoff(row, lchunk));          // dims 0-15
        LDSM4(qf[0], qf[1], qf[2], qf[3], a0);
        u32 a1 = smaddr(sK + swoff(row, 2 + lchunk));      // dims 16-31
        LDSM4(qf[4], qf[5], qf[6], qf[7], a1);
    }

    float o[16];
#pragma unroll
    for (int i = 0; i < 16; i++) o[i] = 0.f;
    float lsum0 = 0.f, lsum1 = 0.f;

    const int kbase = ks * (SS / KS);               // 512 keys per split
    const __nv_bfloat16* gK = g_kb + ((size_t)bh * SS + kbase) * DH;
    const __nv_bfloat16* gV = g_vb + ((size_t)bh * SS + kbase) * DH;

    for (int ch = 0; ch < SS / KS / 128; ch++) {    // 4 chunks of 128 keys
        __syncthreads();
        const uint4* srcK = (const uint4*)(gK + (size_t)ch * 128 * DH);
        const uint4* srcV = (const uint4*)(gV + (size_t)ch * 128 * DH);
        for (int i = tid; i < 512; i += 256) {
            int row = i >> 2, c = i & 3;
            int off = swoff(row, c);
            *(uint4*)(sK + off) = srcK[i];
            *(uint4*)(sV + off) = srcV[i];
        }
        __syncthreads();

#pragma unroll 4
        for (int kt = 0; kt < 8; kt++) {            // 16 keys per step
            int row = kt * 16 + lrow;
            u32 k0[4], k1[4], v0[4], v1[4];
            LDSM4 (k0[0], k0[1], k0[2], k0[3], smaddr(sK + swoff(row, lchunk)));
            LDSM4 (k1[0], k1[1], k1[2], k1[3], smaddr(sK + swoff(row, 2 + lchunk)));
            LDSM4T(v0[0], v0[1], v0[2], v0[3], smaddr(sV + swoff(row, lchunk)));
            LDSM4T(v1[0], v1[1], v1[2], v1[3], smaddr(sV + swoff(row, 2 + lchunk)));

            // scores: S(16q x 16k), f32
            float sA0 = 0.f, sA1 = 0.f, sA2 = 0.f, sA3 = 0.f;   // keys kt*16+0..7
            float sB0 = 0.f, sB1 = 0.f, sB2 = 0.f, sB3 = 0.f;   // keys kt*16+8..15
            MMA(sA0, sA1, sA2, sA3, qf[0], qf[1], qf[2], qf[3], k0[0], k0[2]);
            MMA(sA0, sA1, sA2, sA3, qf[4], qf[5], qf[6], qf[7], k1[0], k1[2]);
            MMA(sB0, sB1, sB2, sB3, qf[0], qf[1], qf[2], qf[3], k0[1], k0[3]);
            MMA(sB0, sB1, sB2, sB3, qf[4], qf[5], qf[6], qf[7], k1[1], k1[3]);

            // p = 2^s  (log2e & 1/sqrt(dh) folded into Q at projection)
            float eA0, eA1, eA2, eA3, eB0, eB1, eB2, eB3;
            EX2(eA0, sA0); EX2(eA1, sA1); EX2(eA2, sA2); EX2(eA3, sA3);
            EX2(eB0, sB0); EX2(eB1, sB1); EX2(eB2, sB2); EX2(eB3, sB3);
            lsum0 += (eA0 + eA1) + (eB0 + eB1);
            lsum1 += (eA2 + eA3) + (eB2 + eB3);

            // P fragment (A-operand layout for mma2)
            u32 p0, p1, p2, p3;
            CVTB2(p0, eA1, eA0);
            CVTB2(p1, eA3, eA2);
            CVTB2(p2, eB1, eB0);
            CVTB2(p3, eB3, eB2);

            // O(16q x 32d) += P(16x16) @ V(16k x 32d)
            MMA(o[0],  o[1],  o[2],  o[3],  p0, p1, p2, p3, v0[0], v0[1]);
            MMA(o[4],  o[5],  o[6],  o[7],  p0, p1, p2, p3, v0[2], v0[3]);
            MMA(o[8],  o[9],  o[10], o[11], p0, p1, p2, p3, v1[0], v1[1]);
            MMA(o[12], o[13], o[14], o[15], p0, p1, p2, p3, v1[2], v1[3]);
        }
    }

    // reduce l across the 4 lanes of each row-quad
    lsum0 += __shfl_xor_sync(0xffffffffu, lsum0, 1);
    lsum0 += __shfl_xor_sync(0xffffffffu, lsum0, 2);
    lsum1 += __shfl_xor_sync(0xffffffffu, lsum1, 1);
    lsum1 += __shfl_xor_sync(0xffffffffu, lsum1, 2);

    int r = lane >> 2, cq = lane & 3;
    int q0 = qt * 128 + w * 16 + r;
    size_t lb = ((size_t)bh * SS + q0) * KS + ks;
    if (cq == 0) {
        g_lpart[lb] = lsum0;
        g_lpart[lb + (size_t)8 * KS] = lsum1;
    }
#pragma unroll
    for (int d = 0; d < 4; d++) {
        size_t ob0 = (((size_t)bh * SS + q0) * KS + ks) * DH + d * 8 + cq * 2;
        *(float2*)(g_opart + ob0) = make_float2(o[d * 4 + 0], o[d * 4 + 1]);
        size_t ob1 = (((size_t)bh * SS + q0 + 8) * KS + ks) * DH + d * 8 + cq * 2;
        *(float2*)(g_opart + ob1) = make_float2(o[d * 4 + 2], o[d * 4 + 3]);
    }
}

// ---------------- 4) combine splits + blend + head interleave ------------
__global__ void __launch_bounds__(256) combine_kernel()
{
    int gid = blockIdx.x * 256 + threadIdx.x;
    int q  = gid >> 3;           // 0..BH*S-1
    int dq = gid & 7;            // float4 index within DH=32
    int bh = q >> 12;
    int p  = q & 4095;

    float l = 0.f;
#pragma unroll
    for (int k = 0; k < KS; k++) l += g_lpart[(size_t)q * KS + k];

    float4 o = make_float4(0.f, 0.f, 0.f, 0.f);
#pragma unroll
    for (int k = 0; k < KS; k++) {
        float4 t = ((const float4*)(g_opart + ((size_t)q * KS + k) * DH))[dq];
        o.x += t.x; o.y += t.y; o.z += t.z; o.w += t.w;
    }
    float inv = 0.5f / l;
    float4 vs = ((const float4*)(g_vsum + bh * DH))[dq];
    float4 z;
    z.x = fmaf(o.x, inv, 0.5f * vs.x);
    z.y = fmaf(o.y, inv, 0.5f * vs.y);
    z.z = fmaf(o.z, inv, 0.5f * vs.z);
    z.w = fmaf(o.w, inv, 0.5f * vs.w);
    int b = bh >> 2, h = bh & 3;
    ((float4*)(g_z + (size_t)(b * SS + p) * DD + h * DH))[dq] = z;
}

// ---------------- 5) output projection: out = z @ W_O^T -------------------
__global__ void __launch_bounds__(128) out_kernel(
    const float* __restrict__ Wo, float* __restrict__ out)
{
    const int R = 16;
    __shared__ __align__(16) float zs[R][DD];
    int rowbase = blockIdx.x * R;
    int tid = threadIdx.x;
    for (int i = tid; i < R * DD; i += 128)
        zs[i / DD][i % DD] = g_z[(size_t)rowbase * DD + i];
    __syncthreads();

    const float4* Wr = (const float4*)(Wo + tid * DD);
    float acc[R];
#pragma unroll
    for (int r = 0; r < R; r++) acc[r] = 0.f;
#pragma unroll 8
    for (int jc = 0; jc < DD / 4; jc++) {
        float4 w = Wr[jc];
#pragma unroll
        for (int r = 0; r < R; r++) {
            float4 zv = *(const float4*)(&zs[r][jc * 4]);
            acc[r] = fmaf(w.x, zv.x, acc[r]);
            acc[r] = fmaf(w.y, zv.y, acc[r]);
            acc[r] = fmaf(w.z, zv.z, acc[r]);
            acc[r] = fmaf(w.w, zv.w, acc[r]);
        }
    }
#pragma unroll
    for (int r = 0; r < R; r++)
        out[(size_t)(rowbase + r) * DD + tid] = acc[r];
}

// ---------------- launch ----------------
extern "C" void kernel_launch(void* const* d_in, const int* in_sizes, int n_in,
                              void* d_out, int out_size)
{
    const float* x  = (const float*)d_in[0];
    const float* Wk = (const float*)d_in[1];
    const float* Wq = (const float*)d_in[2];
    const float* Wv = (const float*)d_in[3];
    const float* Wo = (const float*)d_in[4];
    float* out = (float*)d_out;

    proj_kernel<<<(BB * SS) / 16, 384>>>(x, Wk, Wq, Wv);
    xsum_kernel<<<BB * 8, 512>>>(x);
    vsumw_kernel<<<BHT, 128>>>(Wv);
    {
        dim3 grid(BHT, SS / 128, KS);
        attn_kernel<<<grid, 256>>>();
    }
    combine_kernel<<<(BHT * SS * 8) / 256, 256>>>();
    out_kernel<<<(BB * SS) / 16, 128>>>(Wo, out);
}

// round 4
// speedup vs baseline: 6.4057x; 1.4119x over previous
#include <cuda_runtime.h>
#include <cuda_bf16.h>

#define BB 2
#define SS 4096
#define DD 128
#define HH 4
#define DH 32
#define BHT (BB*HH)
#define KS 8
#define QSCALE 0.17677669529663687f   // 1/sqrt(32)
#define LOG2E  1.4426950408889634f

typedef unsigned int u32;

// ---------------- scratch (device globals; no allocations) ----------------
__device__ __align__(16) __nv_bfloat16 g_qb[(size_t)BHT*SS*DH];
__device__ __align__(16) __nv_bfloat16 g_kb[(size_t)BHT*SS*DH];
__device__ __align__(16) __nv_bfloat16 g_vb[(size_t)BHT*SS*DH];
__device__ __align__(16) __nv_bfloat16 g_xb[(size_t)BB*SS*DD];
__device__ __align__(16) __nv_bfloat16 g_wb[3*128*128];
__device__ __align__(16) float g_xpart[BB*8][DD];
__device__ __align__(16) float g_vsum[BHT*DH];
__device__ __align__(16) float g_lpart[(size_t)BHT*SS*KS];
__device__ __align__(16) float g_opart[(size_t)BHT*SS*KS*DH];

// ---------------- asm helpers ----------------
__device__ __forceinline__ u32 smaddr(const void* p) {
    u32 a;
    asm("{.reg .u64 t; cvta.to.shared.u64 t, %1; cvt.u32.u64 %0, t;}" : "=r"(a) : "l"(p));
    return a;
}
#define LDSM4(r0,r1,r2,r3,a) \
    asm volatile("ldmatrix.sync.aligned.m8n8.x4.shared.b16 {%0,%1,%2,%3},[%4];" \
        : "=r"(r0),"=r"(r1),"=r"(r2),"=r"(r3) : "r"(a))
#define LDSM4T(r0,r1,r2,r3,a) \
    asm volatile("ldmatrix.sync.aligned.m8n8.x4.trans.shared.b16 {%0,%1,%2,%3},[%4];" \
        : "=r"(r0),"=r"(r1),"=r"(r2),"=r"(r3) : "r"(a))
#define MMA(c0,c1,c2,c3,a0,a1,a2,a3,b0,b1) \
    asm volatile("mma.sync.aligned.m16n8k16.row.col.f32.bf16.bf16.f32 " \
        "{%0,%1,%2,%3},{%4,%5,%6,%7},{%8,%9},{%0,%1,%2,%3};" \
        : "+f"(c0),"+f"(c1),"+f"(c2),"+f"(c3) \
        : "r"(a0),"r"(a1),"r"(a2),"r"(a3),"r"(b0),"r"(b1))
#define EX2(d,s) asm("ex2.approx.ftz.f32 %0,%1;" : "=f"(d) : "f"(s))
#define CVTB2(d,hi,lo) asm("cvt.rn.bf16x2.f32 %0,%1,%2;" : "=r"(d) : "f"(hi),"f"(lo))

// swizzle for 32-col bf16 tiles (4 x 16B chunks per row)
__device__ __forceinline__ int swoff(int row, int chunk) {
    return row * 32 + (((chunk) ^ ((row >> 1) & 3)) << 3);
}
// swizzle for 128-col bf16 tiles (16 x 16B chunks per row)
__device__ __forceinline__ int swoff2(int row, int chunk) {
    return row * 128 + ((((chunk ^ row) & 7) | (chunk & 8)) << 3);
}

// ---------------- 0) W -> bf16 (Q pre-scaled) -----------------------------
// g_wb layout: [mat][out][k], mat 0=Q,1=K,2=V
__global__ void __launch_bounds__(256) wcvt_kernel(
    const float* __restrict__ Wk,
    const float* __restrict__ Wq,
    const float* __restrict__ Wv)
{
    int idx = blockIdx.x * 256 + threadIdx.x;   // 0..49151
    int mat = idx >> 14;
    int rem = idx & 16383;
    const float* W = (mat == 0) ? Wq : (mat == 1) ? Wk : Wv;
    float scale = (mat == 0) ? (QSCALE * LOG2E) : 1.0f;
    g_wb[idx] = __float2bfloat16(W[rem] * scale);
}

// ---------------- 1) x column-sum partials + x -> bf16 --------------------
__global__ void __launch_bounds__(512) xsum_kernel(const float* __restrict__ x)
{
    int blk = blockIdx.x;            // 0..15 : b*8 + part
    int d = threadIdx.x & 127;
    int c = threadIdx.x >> 7;        // 0..3
    int b = blk >> 3, part = blk & 7;
    size_t rbase = (size_t)b * SS + part * 512;
    const float* base = x + rbase * DD;
    __nv_bfloat16* xb = g_xb + rbase * DD;
    float s = 0.f;
    for (int j = c; j < 512; j += 4) {
        float v = base[(size_t)j * DD + d];
        s += v;
        xb[(size_t)j * DD + d] = __float2bfloat16(v);
    }
    __shared__ float red[4][DD];
    red[c][d] = s;
    __syncthreads();
    if (c == 0)
        g_xpart[blk][d] = red[0][d] + red[1][d] + red[2][d] + red[3][d];
}

// ---------------- 2) vsum = W_V . xsum (fp32 exact) -----------------------
__global__ void __launch_bounds__(128) vsumw_kernel(const float* __restrict__ Wv)
{
    int bh = blockIdx.x;
    int b = bh >> 2, h = bh & 3;
    __shared__ float xs[DD];
    int tid = threadIdx.x;
    if (tid < DD) {
        float s = 0.f;
#pragma unroll
        for (int p = 0; p < 8; p++) s += g_xpart[b * 8 + p][tid];
        xs[tid] = s;
    }
    __syncthreads();
    if (tid < DH) {
        const float* Wr = Wv + (size_t)(h * DH + tid) * DD;
        float s = 0.f;
#pragma unroll 4
        for (int j = 0; j < DD; j++) s = fmaf(Wr[j], xs[j], s);
        g_vsum[bh * DH + tid] = s;
    }
}

// ---------------- 3) QKV projection via tensor cores ----------------------
// grid (6, 128): blockIdx.x = col tile (64 outs within 3x128), blockIdx.y = 64-row tile
__global__ void __launch_bounds__(128) projmma_kernel()
{
    int bx = blockIdx.x;
    int rowbase = blockIdx.y * 64;
    int mat = bx >> 1;
    int obase = (bx & 1) * 64;
    int tid = threadIdx.x;
    int w = tid >> 5, lane = tid & 31;
    int lrow = lane & 15, lchunk = lane >> 4;
    int r = lane >> 2, cq = lane & 3;

    __shared__ __align__(16) __nv_bfloat16 sX[64 * 128];
    __shared__ __align__(16) __nv_bfloat16 sW[64 * 128];

    const uint4* gX = (const uint4*)(g_xb + (size_t)rowbase * DD);
    const uint4* gW = (const uint4*)(g_wb + (size_t)(mat * 128 + obase) * 128);
    for (int i = tid; i < 1024; i += 128) {
        int row = i >> 4, c = i & 15;
        int off = swoff2(row, c);
        *(uint4*)(sX + off) = gX[i];
        *(uint4*)(sW + off) = gW[i];
    }
    __syncthreads();

    int wr = (w >> 1) * 32, wc = (w & 1) * 32;
    float acc[2][4][4];
#pragma unroll
    for (int i = 0; i < 2; i++)
#pragma unroll
        for (int j = 0; j < 4; j++)
#pragma unroll
            for (int k = 0; k < 4; k++) acc[i][j][k] = 0.f;

#pragma unroll
    for (int ks = 0; ks < 8; ks++) {
        u32 a0[4], a1[4], b0[4], b1[4];
        LDSM4(a0[0], a0[1], a0[2], a0[3], smaddr(sX + swoff2(wr + lrow,      2 * ks + lchunk)));
        LDSM4(a1[0], a1[1], a1[2], a1[3], smaddr(sX + swoff2(wr + 16 + lrow, 2 * ks + lchunk)));
        LDSM4(b0[0], b0[1], b0[2], b0[3], smaddr(sW + swoff2(wc + lrow,      2 * ks + lchunk)));
        LDSM4(b1[0], b1[1], b1[2], b1[3], smaddr(sW + swoff2(wc + 16 + lrow, 2 * ks + lchunk)));
        MMA(acc[0][0][0], acc[0][0][1], acc[0][0][2], acc[0][0][3], a0[0], a0[1], a0[2], a0[3], b0[0], b0[2]);
        MMA(acc[0][1][0], acc[0][1][1], acc[0][1][2], acc[0][1][3], a0[0], a0[1], a0[2], a0[3], b0[1], b0[3]);
        MMA(acc[0][2][0], acc[0][2][1], acc[0][2][2], acc[0][2][3], a0[0], a0[1], a0[2], a0[3], b1[0], b1[2]);
        MMA(acc[0][3][0], acc[0][3][1], acc[0][3][2], acc[0][3][3], a0[0], a0[1], a0[2], a0[3], b1[1], b1[3]);
        MMA(acc[1][0][0], acc[1][0][1], acc[1][0][2], acc[1][0][3], a1[0], a1[1], a1[2], a1[3], b0[0], b0[2]);
        MMA(acc[1][1][0], acc[1][1][1], acc[1][1][2], acc[1][1][3], a1[0], a1[1], a1[2], a1[3], b0[1], b0[3]);
        MMA(acc[1][2][0], acc[1][2][1], acc[1][2][2], acc[1][2][3], a1[0], a1[1], a1[2], a1[3], b1[0], b1[2]);
        MMA(acc[1][3][0], acc[1][3][1], acc[1][3][2], acc[1][3][3], a1[0], a1[1], a1[2], a1[3], b1[1], b1[3]);
    }

    __nv_bfloat16* G = (mat == 0) ? g_qb : (mat == 1) ? g_kb : g_vb;
#pragma unroll
    for (int rg = 0; rg < 2; rg++) {
#pragma unroll
        for (int ng = 0; ng < 4; ng++) {
            int co = obase + wc + ng * 8 + 2 * cq;   // 0..127 within matrix
            int h = co >> 5, d = co & 31;
            int prow0 = rowbase + wr + rg * 16 + r;
            int b = prow0 >> 12, pp = prow0 & 4095;
            size_t base0 = ((size_t)((b * HH + h)) * SS + pp) * DH + d;
            u32 pk0; CVTB2(pk0, acc[rg][ng][1], acc[rg][ng][0]);
            *(u32*)(G + base0) = pk0;
            u32 pk1; CVTB2(pk1, acc[rg][ng][3], acc[rg][ng][2]);
            *(u32*)(G + base0 + (size_t)8 * DH) = pk1;
        }
    }
}

// ---------------- 4) attention core: 32 queries per warp ------------------
// grid (BHT, SS/128, KS), 128 threads (4 warps x 32 queries)
__global__ void __launch_bounds__(128, 3) attn_kernel()
{
    int bh = blockIdx.x;
    int qt = blockIdx.y;
    int ks = blockIdx.z;
    int tid = threadIdx.x;
    int w = tid >> 5, lane = tid & 31;
    int lrow = lane & 15, lchunk = lane >> 4;

    __shared__ __align__(16) __nv_bfloat16 sK[128 * 32];
    __shared__ __align__(16) __nv_bfloat16 sV[128 * 32];

    // ---- stage Q tile (128 q x 32 d) into sK, build 2 A fragments ----
    {
        const uint4* gQ = (const uint4*)(g_qb + ((size_t)bh * SS + qt * 128) * DH);
        for (int i = tid; i < 512; i += 128) {
            int row = i >> 2, c = i & 3;
            *(uint4*)(sK + swoff(row, c)) = gQ[i];
        }
    }
    __syncthreads();
    u32 qf0[8], qf1[8];
    {
        int row0 = w * 32 + lrow;
        LDSM4(qf0[0], qf0[1], qf0[2], qf0[3], smaddr(sK + swoff(row0, lchunk)));
        LDSM4(qf0[4], qf0[5], qf0[6], qf0[7], smaddr(sK + swoff(row0, 2 + lchunk)));
        int row1 = row0 + 16;
        LDSM4(qf1[0], qf1[1], qf1[2], qf1[3], smaddr(sK + swoff(row1, lchunk)));
        LDSM4(qf1[4], qf1[5], qf1[6], qf1[7], smaddr(sK + swoff(row1, 2 + lchunk)));
    }

    float oA[16], oB[16];
#pragma unroll
    for (int i = 0; i < 16; i++) { oA[i] = 0.f; oB[i] = 0.f; }
    float lA0 = 0.f, lA1 = 0.f, lB0 = 0.f, lB1 = 0.f;

    const int kbase = ks * (SS / KS);               // 512 keys per split
    const __nv_bfloat16* gK = g_kb + ((size_t)bh * SS + kbase) * DH;
    const __nv_bfloat16* gV = g_vb + ((size_t)bh * SS + kbase) * DH;

    for (int ch = 0; ch < SS / KS / 128; ch++) {    // 4 chunks of 128 keys
        __syncthreads();
        const uint4* srcK = (const uint4*)(gK + (size_t)ch * 128 * DH);
        const uint4* srcV = (const uint4*)(gV + (size_t)ch * 128 * DH);
        for (int i = tid; i < 512; i += 128) {
            int row = i >> 2, c = i & 3;
            int off = swoff(row, c);
            *(uint4*)(sK + off) = srcK[i];
            *(uint4*)(sV + off) = srcV[i];
        }
        __syncthreads();

#pragma unroll 2
        for (int kt = 0; kt < 8; kt++) {            // 16 keys per step
            int row = kt * 16 + lrow;
            u32 k0[4], k1[4], v0[4], v1[4];
            LDSM4 (k0[0], k0[1], k0[2], k0[3], smaddr(sK + swoff(row, lchunk)));
            LDSM4 (k1[0], k1[1], k1[2], k1[3], smaddr(sK + swoff(row, 2 + lchunk)));
            LDSM4T(v0[0], v0[1], v0[2], v0[3], smaddr(sV + swoff(row, lchunk)));
            LDSM4T(v1[0], v1[1], v1[2], v1[3], smaddr(sV + swoff(row, 2 + lchunk)));

            // ---- group A (queries w*32 .. +15) ----
            {
                float sA0 = 0.f, sA1 = 0.f, sA2 = 0.f, sA3 = 0.f;
                float sB0 = 0.f, sB1 = 0.f, sB2 = 0.f, sB3 = 0.f;
                MMA(sA0, sA1, sA2, sA3, qf0[0], qf0[1], qf0[2], qf0[3], k0[0], k0[2]);
                MMA(sA0, sA1, sA2, sA3, qf0[4], qf0[5], qf0[6], qf0[7], k1[0], k1[2]);
                MMA(sB0, sB1, sB2, sB3, qf0[0], qf0[1], qf0[2], qf0[3], k0[1], k0[3]);
                MMA(sB0, sB1, sB2, sB3, qf0[4], qf0[5], qf0[6], qf0[7], k1[1], k1[3]);
                float eA0, eA1, eA2, eA3, eB0, eB1, eB2, eB3;
                EX2(eA0, sA0); EX2(eA1, sA1); EX2(eA2, sA2); EX2(eA3, sA3);
                EX2(eB0, sB0); EX2(eB1, sB1); EX2(eB2, sB2); EX2(eB3, sB3);
                lA0 += (eA0 + eA1) + (eB0 + eB1);
                lA1 += (eA2 + eA3) + (eB2 + eB3);
                u32 p0, p1, p2, p3;
                CVTB2(p0, eA1, eA0); CVTB2(p1, eA3, eA2);
                CVTB2(p2, eB1, eB0); CVTB2(p3, eB3, eB2);
                MMA(oA[0],  oA[1],  oA[2],  oA[3],  p0, p1, p2, p3, v0[0], v0[1]);
                MMA(oA[4],  oA[5],  oA[6],  oA[7],  p0, p1, p2, p3, v0[2], v0[3]);
                MMA(oA[8],  oA[9],  oA[10], oA[11], p0, p1, p2, p3, v1[0], v1[1]);
                MMA(oA[12], oA[13], oA[14], oA[15], p0, p1, p2, p3, v1[2], v1[3]);
            }
            // ---- group B (queries w*32+16 .. +31) ----
            {
                float sA0 = 0.f, sA1 = 0.f, sA2 = 0.f, sA3 = 0.f;
                float sB0 = 0.f, sB1 = 0.f, sB2 = 0.f, sB3 = 0.f;
                MMA(sA0, sA1, sA2, sA3, qf1[0], qf1[1], qf1[2], qf1[3], k0[0], k0[2]);
                MMA(sA0, sA1, sA2, sA3, qf1[4], qf1[5], qf1[6], qf1[7], k1[0], k1[2]);
                MMA(sB0, sB1, sB2, sB3, qf1[0], qf1[1], qf1[2], qf1[3], k0[1], k0[3]);
                MMA(sB0, sB1, sB2, sB3, qf1[4], qf1[5], qf1[6], qf1[7], k1[1], k1[3]);
                float eA0, eA1, eA2, eA3, eB0, eB1, eB2, eB3;
                EX2(eA0, sA0); EX2(eA1, sA1); EX2(eA2, sA2); EX2(eA3, sA3);
                EX2(eB0, sB0); EX2(eB1, sB1); EX2(eB2, sB2); EX2(eB3, sB3);
                lB0 += (eA0 + eA1) + (eB0 + eB1);
                lB1 += (eA2 + eA3) + (eB2 + eB3);
                u32 p0, p1, p2, p3;
                CVTB2(p0, eA1, eA0); CVTB2(p1, eA3, eA2);
                CVTB2(p2, eB1, eB0); CVTB2(p3, eB3, eB2);
                MMA(oB[0],  oB[1],  oB[2],  oB[3],  p0, p1, p2, p3, v0[0], v0[1]);
                MMA(oB[4],  oB[5],  oB[6],  oB[7],  p0, p1, p2, p3, v0[2], v0[3]);
                MMA(oB[8],  oB[9],  oB[10], oB[11], p0, p1, p2, p3, v1[0], v1[1]);
                MMA(oB[12], oB[13], oB[14], oB[15], p0, p1, p2, p3, v1[2], v1[3]);
            }
        }
    }

    // l reduction across row-quads
    lA0 += __shfl_xor_sync(0xffffffffu, lA0, 1);
    lA0 += __shfl_xor_sync(0xffffffffu, lA0, 2);
    lA1 += __shfl_xor_sync(0xffffffffu, lA1, 1);
    lA1 += __shfl_xor_sync(0xffffffffu, lA1, 2);
    lB0 += __shfl_xor_sync(0xffffffffu, lB0, 1);
    lB0 += __shfl_xor_sync(0xffffffffu, lB0, 2);
    lB1 += __shfl_xor_sync(0xffffffffu, lB1, 1);
    lB1 += __shfl_xor_sync(0xffffffffu, lB1, 2);

    int r = lane >> 2, cq = lane & 3;
    int qgA = qt * 128 + w * 32 + r;
    int qgB = qgA + 16;
    if (cq == 0) {
        g_lpart[((size_t)bh * SS + qgA) * KS + ks]     = lA0;
        g_lpart[((size_t)bh * SS + qgA + 8) * KS + ks] = lA1;
        g_lpart[((size_t)bh * SS + qgB) * KS + ks]     = lB0;
        g_lpart[((size_t)bh * SS + qgB + 8) * KS + ks] = lB1;
    }
#pragma unroll
    for (int d = 0; d < 4; d++) {
        size_t a0 = (((size_t)bh * SS + qgA) * KS + ks) * DH + d * 8 + cq * 2;
        *(float2*)(g_opart + a0) = make_float2(oA[d * 4 + 0], oA[d * 4 + 1]);
        size_t a1 = (((size_t)bh * SS + qgA + 8) * KS + ks) * DH + d * 8 + cq * 2;
        *(float2*)(g_opart + a1) = make_float2(oA[d * 4 + 2], oA[d * 4 + 3]);
        size_t b0 = (((size_t)bh * SS + qgB) * KS + ks) * DH + d * 8 + cq * 2;
        *(float2*)(g_opart + b0) = make_float2(oB[d * 4 + 0], oB[d * 4 + 1]);
        size_t b1 = (((size_t)bh * SS + qgB + 8) * KS + ks) * DH + d * 8 + cq * 2;
        *(float2*)(g_opart + b1) = make_float2(oB[d * 4 + 2], oB[d * 4 + 3]);
    }
}

// ---------------- 5) fused combine + output projection --------------------
__global__ void __launch_bounds__(128) outfused_kernel(
    const float* __restrict__ Wo, float* __restrict__ out)
{
    const int R = 16;
    __shared__ __align__(16) float zs[R][DD];
    __shared__ float ls[R][HH];
    int rowbase = blockIdx.x * R;
    int tid = threadIdx.x;

    // phase A: per-(row, head) inverse-l
    if (tid < R * HH) {
        int rr = tid >> 2, h = tid & 3;
        int grow = rowbase + rr;
        int b = grow >> 12, p = grow & 4095;
        int bh = b * HH + h;
        float l = 0.f;
#pragma unroll
        for (int k = 0; k < KS; k++) l += g_lpart[((size_t)bh * SS + p) * KS + k];
        ls[rr][h] = 0.5f / l;
    }
    __syncthreads();

    // phase B: build z tile
#pragma unroll
    for (int rr4 = 0; rr4 < 4; rr4++) {
        int e = rr4 * 128 + tid;          // float4 element 0..511
        int row = e >> 5, fq = e & 31;    // fq: float4 index within 128-col row
        int h = fq >> 3, dq = fq & 7;
        int grow = rowbase + row;
        int b = grow >> 12, p = grow & 4095;
        int bh = b * HH + h;
        float4 o = make_float4(0.f, 0.f, 0.f, 0.f);
#pragma unroll
        for (int k = 0; k < KS; k++) {
            float4 t = ((const float4*)(g_opart + (((size_t)bh * SS + p) * KS + k) * DH))[dq];
            o.x += t.x; o.y += t.y; o.z += t.z; o.w += t.w;
        }
        float inv = ls[row][h];
        float4 vs = ((const float4*)(g_vsum + bh * DH))[dq];
        float4 z;
        z.x = fmaf(o.x, inv, 0.5f * vs.x);
        z.y = fmaf(o.y, inv, 0.5f * vs.y);
        z.z = fmaf(o.z, inv, 0.5f * vs.z);
        z.w = fmaf(o.w, inv, 0.5f * vs.w);
        *(float4*)(&zs[row][fq * 4]) = z;
    }
    __syncthreads();

    // phase C: out = z @ Wo^T
    const float4* Wr = (const float4*)(Wo + tid * DD);
    float acc[R];
#pragma unroll
    for (int r = 0; r < R; r++) acc[r] = 0.f;
#pragma unroll 8
    for (int jc = 0; jc < DD / 4; jc++) {
        float4 w = Wr[jc];
#pragma unroll
        for (int r = 0; r < R; r++) {
            float4 zv = *(const float4*)(&zs[r][jc * 4]);
            acc[r] = fmaf(w.x, zv.x, acc[r]);
            acc[r] = fmaf(w.y, zv.y, acc[r]);
            acc[r] = fmaf(w.z, zv.z, acc[r]);
            acc[r] = fmaf(w.w, zv.w, acc[r]);
        }
    }
#pragma unroll
    for (int r = 0; r < R; r++)
        out[(size_t)(rowbase + r) * DD + tid] = acc[r];
}

// ---------------- launch ----------------
extern "C" void kernel_launch(void* const* d_in, const int* in_sizes, int n_in,
                              void* d_out, int out_size)
{
    const float* x  = (const float*)d_in[0];
    const float* Wk = (const float*)d_in[1];
    const float* Wq = (const float*)d_in[2];
    const float* Wv = (const float*)d_in[3];
    const float* Wo = (const float*)d_in[4];
    float* out = (float*)d_out;

    wcvt_kernel<<<192, 256>>>(Wk, Wq, Wv);
    xsum_kernel<<<BB * 8, 512>>>(x);
    vsumw_kernel<<<BHT, 128>>>(Wv);
    projmma_kernel<<<dim3(6, (BB * SS) / 64), 128>>>();
    {
        dim3 grid(BHT, SS / 128, KS);
        attn_kernel<<<grid, 128>>>();
    }
    outfused_kernel<<<(BB * SS) / 16, 128>>>(Wo, out);
}

// round 5
// speedup vs baseline: 7.3801x; 1.1521x over previous
#include <cuda_runtime.h>
#include <cuda_bf16.h>

#define BB 2
#define SS 4096
#define DD 128
#define HH 4
#define DH 32
#define BHT (BB*HH)
#define KS 8
#define QSCALE 0.17677669529663687f   // 1/sqrt(32)
#define LOG2E  1.4426950408889634f

typedef unsigned int u32;

// ---------------- scratch (device globals; no allocations) ----------------
__device__ __align__(16) __nv_bfloat16 g_qb[(size_t)BHT*SS*DH];
__device__ __align__(16) __nv_bfloat16 g_kb[(size_t)BHT*SS*DH];
__device__ __align__(16) __nv_bfloat16 g_vb[(size_t)BHT*SS*DH];
__device__ __align__(16) __nv_bfloat16 g_xb[(size_t)BB*SS*DD];
__device__ __align__(16) __nv_bfloat16 g_wb[3*128*128];
__device__ __align__(16) float g_xpart[BB*32][DD];
__device__ __align__(16) float g_vsum[BHT*DH];
__device__ __align__(16) float g_lpart[(size_t)BHT*SS*KS];
__device__ __align__(16) __nv_bfloat16 g_opartb[(size_t)BHT*SS*KS*DH];

// ---------------- asm helpers ----------------
__device__ __forceinline__ u32 smaddr(const void* p) {
    u32 a;
    asm("{.reg .u64 t; cvta.to.shared.u64 t, %1; cvt.u32.u64 %0, t;}" : "=r"(a) : "l"(p));
    return a;
}
#define LDSM4(r0,r1,r2,r3,a) \
    asm volatile("ldmatrix.sync.aligned.m8n8.x4.shared.b16 {%0,%1,%2,%3},[%4];" \
        : "=r"(r0),"=r"(r1),"=r"(r2),"=r"(r3) : "r"(a))
#define LDSM4T(r0,r1,r2,r3,a) \
    asm volatile("ldmatrix.sync.aligned.m8n8.x4.trans.shared.b16 {%0,%1,%2,%3},[%4];" \
        : "=r"(r0),"=r"(r1),"=r"(r2),"=r"(r3) : "r"(a))
#define MMA(c0,c1,c2,c3,a0,a1,a2,a3,b0,b1) \
    asm volatile("mma.sync.aligned.m16n8k16.row.col.f32.bf16.bf16.f32 " \
        "{%0,%1,%2,%3},{%4,%5,%6,%7},{%8,%9},{%0,%1,%2,%3};" \
        : "+f"(c0),"+f"(c1),"+f"(c2),"+f"(c3) \
        : "r"(a0),"r"(a1),"r"(a2),"r"(a3),"r"(b0),"r"(b1))
#define EX2(d,s) asm("ex2.approx.ftz.f32 %0,%1;" : "=f"(d) : "f"(s))
#define CVTB2(d,hi,lo) asm("cvt.rn.bf16x2.f32 %0,%1,%2;" : "=r"(d) : "f"(hi),"f"(lo))
#define CPASYNC16(sa, ga) asm volatile("cp.async.cg.shared.global [%0],[%1],16;" :: "r"(sa),"l"(ga))
#define CPCOMMIT() asm volatile("cp.async.commit_group;" ::: "memory")
#define CPWAIT(n)  asm volatile("cp.async.wait_group %0;" :: "n"(n) : "memory")

// swizzle for 32-col bf16 tiles (4 x 16B chunks per row)
__device__ __forceinline__ int swoff(int row, int chunk) {
    return row * 32 + (((chunk) ^ ((row >> 1) & 3)) << 3);
}
// swizzle for 128-col bf16 tiles (16 x 16B chunks per row)
__device__ __forceinline__ int swoff2(int row, int chunk) {
    return row * 128 + ((((chunk ^ row) & 7) | (chunk & 8)) << 3);
}

// ---------------- 0) W -> bf16 (Q pre-scaled) -----------------------------
__global__ void __launch_bounds__(256) wcvt_kernel(
    const float* __restrict__ Wk,
    const float* __restrict__ Wq,
    const float* __restrict__ Wv)
{
    int idx = blockIdx.x * 256 + threadIdx.x;   // 0..49151
    int mat = idx >> 14;
    int rem = idx & 16383;
    const float* W = (mat == 0) ? Wq : (mat == 1) ? Wk : Wv;
    float scale = (mat == 0) ? (QSCALE * LOG2E) : 1.0f;
    g_wb[idx] = __float2bfloat16(W[rem] * scale);
}

// ---------------- 1) x column-sum partials + x -> bf16 --------------------
// grid 64 blocks x 256 threads, 128 rows per block
__global__ void __launch_bounds__(256) xsum_kernel(const float* __restrict__ x)
{
    int blk = blockIdx.x;            // 0..63 : b*32 + part
    int d = threadIdx.x & 127;
    int c = threadIdx.x >> 7;        // 0..1
    int b = blk >> 5, part = blk & 31;
    size_t rbase = (size_t)b * SS + part * 128;
    const float* base = x + rbase * DD;
    __nv_bfloat16* xb = g_xb + rbase * DD;
    float s = 0.f;
    for (int j = c; j < 128; j += 2) {
        float v = base[(size_t)j * DD + d];
        s += v;
        xb[(size_t)j * DD + d] = __float2bfloat16(v);
    }
    __shared__ float red[2][DD];
    red[c][d] = s;
    __syncthreads();
    if (c == 0)
        g_xpart[blk][d] = red[0][d] + red[1][d];
}

// ---------------- 2) vsum = W_V . xsum (fp32 exact) -----------------------
__global__ void __launch_bounds__(128) vsumw_kernel(const float* __restrict__ Wv)
{
    int bh = blockIdx.x;
    int b = bh >> 2, h = bh & 3;
    __shared__ float xs[DD];
    int tid = threadIdx.x;
    if (tid < DD) {
        float s = 0.f;
#pragma unroll
        for (int p = 0; p < 32; p++) s += g_xpart[b * 32 + p][tid];
        xs[tid] = s;
    }
    __syncthreads();
    if (tid < DH) {
        const float* Wr = Wv + (size_t)(h * DH + tid) * DD;
        float s = 0.f;
#pragma unroll 4
        for (int j = 0; j < DD; j++) s = fmaf(Wr[j], xs[j], s);
        g_vsum[bh * DH + tid] = s;
    }
}

// ---------------- 3) QKV projection via tensor cores ----------------------
__global__ void __launch_bounds__(128) projmma_kernel()
{
    int bx = blockIdx.x;
    int rowbase = blockIdx.y * 64;
    int mat = bx >> 1;
    int obase = (bx & 1) * 64;
    int tid = threadIdx.x;
    int w = tid >> 5, lane = tid & 31;
    int lrow = lane & 15, lchunk = lane >> 4;
    int r = lane >> 2, cq = lane & 3;

    __shared__ __align__(16) __nv_bfloat16 sX[64 * 128];
    __shared__ __align__(16) __nv_bfloat16 sW[64 * 128];

    const uint4* gX = (const uint4*)(g_xb + (size_t)rowbase * DD);
    const uint4* gW = (const uint4*)(g_wb + (size_t)(mat * 128 + obase) * 128);
    for (int i = tid; i < 1024; i += 128) {
        int row = i >> 4, c = i & 15;
        int off = swoff2(row, c);
        CPASYNC16(smaddr(sX + off), gX + i);
        CPASYNC16(smaddr(sW + off), gW + i);
    }
    CPCOMMIT();
    CPWAIT(0);
    __syncthreads();

    int wr = (w >> 1) * 32, wc = (w & 1) * 32;
    float acc[2][4][4];
#pragma unroll
    for (int i = 0; i < 2; i++)
#pragma unroll
        for (int j = 0; j < 4; j++)
#pragma unroll
            for (int k = 0; k < 4; k++) acc[i][j][k] = 0.f;

#pragma unroll
    for (int ks = 0; ks < 8; ks++) {
        u32 a0[4], a1[4], b0[4], b1[4];
        LDSM4(a0[0], a0[1], a0[2], a0[3], smaddr(sX + swoff2(wr + lrow,      2 * ks + lchunk)));
        LDSM4(a1[0], a1[1], a1[2], a1[3], smaddr(sX + swoff2(wr + 16 + lrow, 2 * ks + lchunk)));
        LDSM4(b0[0], b0[1], b0[2], b0[3], smaddr(sW + swoff2(wc + lrow,      2 * ks + lchunk)));
        LDSM4(b1[0], b1[1], b1[2], b1[3], smaddr(sW + swoff2(wc + 16 + lrow, 2 * ks + lchunk)));
        MMA(acc[0][0][0], acc[0][0][1], acc[0][0][2], acc[0][0][3], a0[0], a0[1], a0[2], a0[3], b0[0], b0[2]);
        MMA(acc[0][1][0], acc[0][1][1], acc[0][1][2], acc[0][1][3], a0[0], a0[1], a0[2], a0[3], b0[1], b0[3]);
        MMA(acc[0][2][0], acc[0][2][1], acc[0][2][2], acc[0][2][3], a0[0], a0[1], a0[2], a0[3], b1[0], b1[2]);
        MMA(acc[0][3][0], acc[0][3][1], acc[0][3][2], acc[0][3][3], a0[0], a0[1], a0[2], a0[3], b1[1], b1[3]);
        MMA(acc[1][0][0], acc[1][0][1], acc[1][0][2], acc[1][0][3], a1[0], a1[1], a1[2], a1[3], b0[0], b0[2]);
        MMA(acc[1][1][0], acc[1][1][1], acc[1][1][2], acc[1][1][3], a1[0], a1[1], a1[2], a1[3], b0[1], b0[3]);
        MMA(acc[1][2][0], acc[1][2][1], acc[1][2][2], acc[1][2][3], a1[0], a1[1], a1[2], a1[3], b1[0], b1[2]);
        MMA(acc[1][3][0], acc[1][3][1], acc[1][3][2], acc[1][3][3], a1[0], a1[1], a1[2], a1[3], b1[1], b1[3]);
    }

    __nv_bfloat16* G = (mat == 0) ? g_qb : (mat == 1) ? g_kb : g_vb;
#pragma unroll
    for (int rg = 0; rg < 2; rg++) {
#pragma unroll
        for (int ng = 0; ng < 4; ng++) {
            int co = obase + wc + ng * 8 + 2 * cq;   // 0..127 within matrix
            int h = co >> 5, d = co & 31;
            int prow0 = rowbase + wr + rg * 16 + r;
            int b = prow0 >> 12, pp = prow0 & 4095;
            size_t base0 = ((size_t)((b * HH + h)) * SS + pp) * DH + d;
            u32 pk0; CVTB2(pk0, acc[rg][ng][1], acc[rg][ng][0]);
            *(u32*)(G + base0) = pk0;
            u32 pk1; CVTB2(pk1, acc[rg][ng][3], acc[rg][ng][2]);
            *(u32*)(G + base0 + (size_t)8 * DH) = pk1;
        }
    }
}

// ---------------- 4) attention core: 32 q/warp, cp.async double buffer ----
// grid (BHT, SS/128, KS), 128 threads (4 warps)
__global__ void __launch_bounds__(128, 3) attn_kernel()
{
    int bh = blockIdx.x;
    int qt = blockIdx.y;
    int ks = blockIdx.z;
    int tid = threadIdx.x;
    int w = tid >> 5, lane = tid & 31;
    int lrow = lane & 15, lchunk = lane >> 4;

    __shared__ __align__(16) __nv_bfloat16 sK[2][128 * 32];
    __shared__ __align__(16) __nv_bfloat16 sV[2][128 * 32];

    // ---- stage Q tile into sK[0], extract 2 A fragments ----
    {
        const uint4* gQ = (const uint4*)(g_qb + ((size_t)bh * SS + qt * 128) * DH);
        for (int i = tid; i < 512; i += 128) {
            int row = i >> 2, c = i & 3;
            *(uint4*)(sK[0] + swoff(row, c)) = gQ[i];
        }
    }
    __syncthreads();
    u32 qf0[8], qf1[8];
    {
        int row0 = w * 32 + lrow;
        LDSM4(qf0[0], qf0[1], qf0[2], qf0[3], smaddr(sK[0] + swoff(row0, lchunk)));
        LDSM4(qf0[4], qf0[5], qf0[6], qf0[7], smaddr(sK[0] + swoff(row0, 2 + lchunk)));
        int row1 = row0 + 16;
        LDSM4(qf1[0], qf1[1], qf1[2], qf1[3], smaddr(sK[0] + swoff(row1, lchunk)));
        LDSM4(qf1[4], qf1[5], qf1[6], qf1[7], smaddr(sK[0] + swoff(row1, 2 + lchunk)));
    }
    __syncthreads();   // everyone done reading Q before cp.async overwrites sK[0]

    float oA[16], oB[16];
#pragma unroll
    for (int i = 0; i < 16; i++) { oA[i] = 0.f; oB[i] = 0.f; }
    float lA0 = 0.f, lA1 = 0.f, lB0 = 0.f, lB1 = 0.f;

    const int kbase = ks * (SS / KS);               // 512 keys per split
    const __nv_bfloat16* gK = g_kb + ((size_t)bh * SS + kbase) * DH;
    const __nv_bfloat16* gV = g_vb + ((size_t)bh * SS + kbase) * DH;
    const int NCH = SS / KS / 128;                  // 4 chunks

    // prefetch chunk 0
    {
        const uint4* srcK = (const uint4*)gK;
        const uint4* srcV = (const uint4*)gV;
        for (int i = tid; i < 512; i += 128) {
            int row = i >> 2, c = i & 3;
            int off = swoff(row, c);
            CPASYNC16(smaddr(sK[0] + off), srcK + i);
            CPASYNC16(smaddr(sV[0] + off), srcV + i);
        }
        CPCOMMIT();
    }

    for (int ch = 0; ch < NCH; ch++) {
        int buf = ch & 1;
        if (ch + 1 < NCH) {
            const uint4* srcK = (const uint4*)(gK + (size_t)(ch + 1) * 128 * DH);
            const uint4* srcV = (const uint4*)(gV + (size_t)(ch + 1) * 128 * DH);
            int nb = buf ^ 1;
            for (int i = tid; i < 512; i += 128) {
                int row = i >> 2, c = i & 3;
                int off = swoff(row, c);
                CPASYNC16(smaddr(sK[nb] + off), srcK + i);
                CPASYNC16(smaddr(sV[nb] + off), srcV + i);
            }
            CPCOMMIT();
            CPWAIT(1);
        } else {
            CPWAIT(0);
        }
        __syncthreads();

#pragma unroll 2
        for (int kt = 0; kt < 8; kt++) {            // 16 keys per step
            int row = kt * 16 + lrow;
            u32 k0[4], k1[4], v0[4], v1[4];
            LDSM4 (k0[0], k0[1], k0[2], k0[3], smaddr(sK[buf] + swoff(row, lchunk)));
            LDSM4 (k1[0], k1[1], k1[2], k1[3], smaddr(sK[buf] + swoff(row, 2 + lchunk)));
            LDSM4T(v0[0], v0[1], v0[2], v0[3], smaddr(sV[buf] + swoff(row, lchunk)));
            LDSM4T(v1[0], v1[1], v1[2], v1[3], smaddr(sV[buf] + swoff(row, 2 + lchunk)));

            // ---- group A (queries w*32 .. +15) ----
            {
                float sA0 = 0.f, sA1 = 0.f, sA2 = 0.f, sA3 = 0.f;
                float sB0 = 0.f, sB1 = 0.f, sB2 = 0.f, sB3 = 0.f;
                MMA(sA0, sA1, sA2, sA3, qf0[0], qf0[1], qf0[2], qf0[3], k0[0], k0[2]);
                MMA(sA0, sA1, sA2, sA3, qf0[4], qf0[5], qf0[6], qf0[7], k1[0], k1[2]);
                MMA(sB0, sB1, sB2, sB3, qf0[0], qf0[1], qf0[2], qf0[3], k0[1], k0[3]);
                MMA(sB0, sB1, sB2, sB3, qf0[4], qf0[5], qf0[6], qf0[7], k1[1], k1[3]);
                float eA0, eA1, eA2, eA3, eB0, eB1, eB2, eB3;
                EX2(eA0, sA0); EX2(eA1, sA1); EX2(eA2, sA2); EX2(eA3, sA3);
                EX2(eB0, sB0); EX2(eB1, sB1); EX2(eB2, sB2); EX2(eB3, sB3);
                lA0 += (eA0 + eA1) + (eB0 + eB1);
                lA1 += (eA2 + eA3) + (eB2 + eB3);
                u32 p0, p1, p2, p3;
                CVTB2(p0, eA1, eA0); CVTB2(p1, eA3, eA2);
                CVTB2(p2, eB1, eB0); CVTB2(p3, eB3, eB2);
                MMA(oA[0],  oA[1],  oA[2],  oA[3],  p0, p1, p2, p3, v0[0], v0[1]);
                MMA(oA[4],  oA[5],  oA[6],  oA[7],  p0, p1, p2, p3, v0[2], v0[3]);
                MMA(oA[8],  oA[9],  oA[10], oA[11], p0, p1, p2, p3, v1[0], v1[1]);
                MMA(oA[12], oA[13], oA[14], oA[15], p0, p1, p2, p3, v1[2], v1[3]);
            }
            // ---- group B (queries w*32+16 .. +31) ----
            {
                float sA0 = 0.f, sA1 = 0.f, sA2 = 0.f, sA3 = 0.f;
                float sB0 = 0.f, sB1 = 0.f, sB2 = 0.f, sB3 = 0.f;
                MMA(sA0, sA1, sA2, sA3, qf1[0], qf1[1], qf1[2], qf1[3], k0[0], k0[2]);
                MMA(sA0, sA1, sA2, sA3, qf1[4], qf1[5], qf1[6], qf1[7], k1[0], k1[2]);
                MMA(sB0, sB1, sB2, sB3, qf1[0], qf1[1], qf1[2], qf1[3], k0[1], k0[3]);
                MMA(sB0, sB1, sB2, sB3, qf1[4], qf1[5], qf1[6], qf1[7], k1[1], k1[3]);
                float eA0, eA1, eA2, eA3, eB0, eB1, eB2, eB3;
                EX2(eA0, sA0); EX2(eA1, sA1); EX2(eA2, sA2); EX2(eA3, sA3);
                EX2(eB0, sB0); EX2(eB1, sB1); EX2(eB2, sB2); EX2(eB3, sB3);
                lB0 += (eA0 + eA1) + (eB0 + eB1);
                lB1 += (eA2 + eA3) + (eB2 + eB3);
                u32 p0, p1, p2, p3;
                CVTB2(p0, eA1, eA0); CVTB2(p1, eA3, eA2);
                CVTB2(p2, eB1, eB0); CVTB2(p3, eB3, eB2);
                MMA(oB[0],  oB[1],  oB[2],  oB[3],  p0, p1, p2, p3, v0[0], v0[1]);
                MMA(oB[4],  oB[5],  oB[6],  oB[7],  p0, p1, p2, p3, v0[2], v0[3]);
                MMA(oB[8],  oB[9],  oB[10], oB[11], p0, p1, p2, p3, v1[0], v1[1]);
                MMA(oB[12], oB[13], oB[14], oB[15], p0, p1, p2, p3, v1[2], v1[3]);
            }
        }
        __syncthreads();
    }

    // l reduction across row-quads
    lA0 += __shfl_xor_sync(0xffffffffu, lA0, 1);
    lA0 += __shfl_xor_sync(0xffffffffu, lA0, 2);
    lA1 += __shfl_xor_sync(0xffffffffu, lA1, 1);
    lA1 += __shfl_xor_sync(0xffffffffu, lA1, 2);
    lB0 += __shfl_xor_sync(0xffffffffu, lB0, 1);
    lB0 += __shfl_xor_sync(0xffffffffu, lB0, 2);
    lB1 += __shfl_xor_sync(0xffffffffu, lB1, 1);
    lB1 += __shfl_xor_sync(0xffffffffu, lB1, 2);

    int r = lane >> 2, cq = lane & 3;
    int qgA = qt * 128 + w * 32 + r;
    int qgB = qgA + 16;
    if (cq == 0) {
        g_lpart[((size_t)bh * SS + qgA) * KS + ks]     = lA0;
        g_lpart[((size_t)bh * SS + qgA + 8) * KS + ks] = lA1;
        g_lpart[((size_t)bh * SS + qgB) * KS + ks]     = lB0;
        g_lpart[((size_t)bh * SS + qgB + 8) * KS + ks] = lB1;
    }
#pragma unroll
    for (int d = 0; d < 4; d++) {
        u32 pk;
        CVTB2(pk, oA[d * 4 + 1], oA[d * 4 + 0]);
        *(u32*)(g_opartb + (((size_t)bh * SS + qgA) * KS + ks) * DH + d * 8 + cq * 2) = pk;
        CVTB2(pk, oA[d * 4 + 3], oA[d * 4 + 2]);
        *(u32*)(g_opartb + (((size_t)bh * SS + qgA + 8) * KS + ks) * DH + d * 8 + cq * 2) = pk;
        CVTB2(pk, oB[d * 4 + 1], oB[d * 4 + 0]);
        *(u32*)(g_opartb + (((size_t)bh * SS + qgB) * KS + ks) * DH + d * 8 + cq * 2) = pk;
        CVTB2(pk, oB[d * 4 + 3], oB[d * 4 + 2]);
        *(u32*)(g_opartb + (((size_t)bh * SS + qgB + 8) * KS + ks) * DH + d * 8 + cq * 2) = pk;
    }
}

// ---------------- 5) fused combine + output projection --------------------
__global__ void __launch_bounds__(128) outfused_kernel(
    const float* __restrict__ Wo, float* __restrict__ out)
{
    const int R = 16;
    __shared__ __align__(16) float zs[R][DD];
    __shared__ float ls[R][HH];
    int rowbase = blockIdx.x * R;
    int tid = threadIdx.x;

    // phase A: per-(row, head) inverse-l
    if (tid < R * HH) {
        int rr = tid >> 2, h = tid & 3;
        int grow = rowbase + rr;
        int b = grow >> 12, p = grow & 4095;
        int bh = b * HH + h;
        float l = 0.f;
#pragma unroll
        for (int k = 0; k < KS; k++) l += g_lpart[((size_t)bh * SS + p) * KS + k];
        ls[rr][h] = 0.5f / l;
    }
    __syncthreads();

    // phase B: build z tile
#pragma unroll
    for (int rr4 = 0; rr4 < 4; rr4++) {
        int e = rr4 * 128 + tid;          // 0..511 : 4-wide d chunk
        int row = e >> 5, fq = e & 31;
        int h = fq >> 3, dq = fq & 7;
        int grow = rowbase + row;
        int b = grow >> 12, p = grow & 4095;
        int bh = b * HH + h;
        float ox = 0.f, oy = 0.f, oz = 0.f, ow = 0.f;
#pragma unroll
        for (int k = 0; k < KS; k++) {
            uint2 t = ((const uint2*)(g_opartb + (((size_t)bh * SS + p) * KS + k) * DH))[dq];
            float2 lo = __bfloat1622float2(*(const __nv_bfloat162*)&t.x);
            float2 hi = __bfloat1622float2(*(const __nv_bfloat162*)&t.y);
            ox += lo.x; oy += lo.y; oz += hi.x; ow += hi.y;
        }
        float inv = ls[row][h];
        float4 vs = ((const float4*)(g_vsum + bh * DH))[dq];
        float4 z;
        z.x = fmaf(ox, inv, 0.5f * vs.x);
        z.y = fmaf(oy, inv, 0.5f * vs.y);
        z.z = fmaf(oz, inv, 0.5f * vs.z);
        z.w = fmaf(ow, inv, 0.5f * vs.w);
        *(float4*)(&zs[row][fq * 4]) = z;
    }
    __syncthreads();

    // phase C: out = z @ Wo^T
    const float4* Wr = (const float4*)(Wo + tid * DD);
    float acc[R];
#pragma unroll
    for (int r = 0; r < R; r++) acc[r] = 0.f;
#pragma unroll 8
    for (int jc = 0; jc < DD / 4; jc++) {
        float4 w = Wr[jc];
#pragma unroll
        for (int r = 0; r < R; r++) {
            float4 zv = *(const float4*)(&zs[r][jc * 4]);
            acc[r] = fmaf(w.x, zv.x, acc[r]);
            acc[r] = fmaf(w.y, zv.y, acc[r]);
            acc[r] = fmaf(w.z, zv.z, acc[r]);
            acc[r] = fmaf(w.w, zv.w, acc[r]);
        }
    }
#pragma unroll
    for (int r = 0; r < R; r++)
        out[(size_t)(rowbase + r) * DD + tid] = acc[r];
}

// ---------------- launch ----------------
extern "C" void kernel_launch(void* const* d_in, const int* in_sizes, int n_in,
                              void* d_out, int out_size)
{
    const float* x  = (const float*)d_in[0];
    const float* Wk = (const float*)d_in[1];
    const float* Wq = (const float*)d_in[2];
    const float* Wv = (const float*)d_in[3];
    const float* Wo = (const float*)d_in[4];
    float* out = (float*)d_out;

    wcvt_kernel<<<192, 256>>>(Wk, Wq, Wv);
    xsum_kernel<<<BB * 32, 256>>>(x);
    vsumw_kernel<<<BHT, 128>>>(Wv);
    projmma_kernel<<<dim3(6, (BB * SS) / 64), 128>>>();
    {
        dim3 grid(BHT, SS / 128, KS);
        attn_kernel<<<grid, 128>>>();
    }
    outfused_kernel<<<(BB * SS) / 16, 128>>>(Wo, out);
}

// round 6
// speedup vs baseline: 7.4949x; 1.0155x over previous
#include <cuda_runtime.h>
#include <cuda_fp16.h>
#include <cuda_bf16.h>

#define BB 2
#define SS 4096
#define DD 128
#define HH 4
#define DH 32
#define BHT (BB*HH)
#define KS 4
#define QSCALE 0.17677669529663687f   // 1/sqrt(32)
#define LOG2E  1.4426950408889634f

typedef unsigned int u32;

// ---------------- scratch (device globals; no allocations) ----------------
__device__ __align__(16) __half g_qh[(size_t)BHT*SS*DH];
__device__ __align__(16) __half g_kh[(size_t)BHT*SS*DH];
__device__ __align__(16) __half g_vh[(size_t)BHT*SS*DH];
__device__ __align__(16) __half g_xh[(size_t)BB*SS*DD];
__device__ __align__(16) __half g_wh[3*128*128];
__device__ __align__(16) float g_xpart[BB*32][DD];
__device__ __align__(16) float g_vsum[BHT*DH];
__device__ __align__(16) float g_lpart[(size_t)BHT*SS*KS];
__device__ __align__(16) __nv_bfloat16 g_opartb[(size_t)BHT*SS*KS*DH];

// ---------------- asm helpers ----------------
__device__ __forceinline__ u32 smaddr(const void* p) {
    u32 a;
    asm("{.reg .u64 t; cvta.to.shared.u64 t, %1; cvt.u32.u64 %0, t;}" : "=r"(a) : "l"(p));
    return a;
}
#define LDSM4(r0,r1,r2,r3,a) \
    asm volatile("ldmatrix.sync.aligned.m8n8.x4.shared.b16 {%0,%1,%2,%3},[%4];" \
        : "=r"(r0),"=r"(r1),"=r"(r2),"=r"(r3) : "r"(a))
#define LDSM4T(r0,r1,r2,r3,a) \
    asm volatile("ldmatrix.sync.aligned.m8n8.x4.trans.shared.b16 {%0,%1,%2,%3},[%4];" \
        : "=r"(r0),"=r"(r1),"=r"(r2),"=r"(r3) : "r"(a))
#define MMAH(c0,c1,c2,c3,a0,a1,a2,a3,b0,b1) \
    asm volatile("mma.sync.aligned.m16n8k16.row.col.f32.f16.f16.f32 " \
        "{%0,%1,%2,%3},{%4,%5,%6,%7},{%8,%9},{%0,%1,%2,%3};" \
        : "+f"(c0),"+f"(c1),"+f"(c2),"+f"(c3) \
        : "r"(a0),"r"(a1),"r"(a2),"r"(a3),"r"(b0),"r"(b1))
#define CVTB2(d,hi,lo) asm("cvt.rn.bf16x2.f32 %0,%1,%2;" : "=r"(d) : "f"(hi),"f"(lo))
#define CVTH2(d,hi,lo) asm("cvt.rn.f16x2.f32 %0,%1,%2;" : "=r"(d) : "f"(hi),"f"(lo))
#define EX2H2(d,s) asm("ex2.approx.f16x2 %0,%1;" : "=r"(d) : "r"(s))
#define HADD2(d,a,b) asm("add.rn.f16x2 %0,%1,%2;" : "=r"(d) : "r"(a),"r"(b))
#define H2TOF2(lo,hi,v) \
    asm("{.reg .f16 l,h; mov.b32 {l,h}, %2; cvt.f32.f16 %0, l; cvt.f32.f16 %1, h;}" \
        : "=f"(lo), "=f"(hi) : "r"(v))
#define CPASYNC16(sa, ga) asm volatile("cp.async.cg.shared.global [%0],[%1],16;" :: "r"(sa),"l"(ga))
#define CPCOMMIT() asm volatile("cp.async.commit_group;" ::: "memory")
#define CPWAIT(n)  asm volatile("cp.async.wait_group %0;" :: "n"(n) : "memory")

// swizzle for 32-col 16-bit tiles (4 x 16B chunks per row)
__device__ __forceinline__ int swoff(int row, int chunk) {
    return row * 32 + (((chunk) ^ ((row >> 1) & 3)) << 3);
}
// swizzle for 128-col 16-bit tiles (16 x 16B chunks per row)
__device__ __forceinline__ int swoff2(int row, int chunk) {
    return row * 128 + ((((chunk ^ row) & 7) | (chunk & 8)) << 3);
}

// ---------------- 0) W -> fp16 (Q pre-scaled) -----------------------------
__global__ void __launch_bounds__(256) wcvt_kernel(
    const float* __restrict__ Wk,
    const float* __restrict__ Wq,
    const float* __restrict__ Wv)
{
    int idx = blockIdx.x * 256 + threadIdx.x;   // 0..49151
    int mat = idx >> 14;
    int rem = idx & 16383;
    const float* W = (mat == 0) ? Wq : (mat == 1) ? Wk : Wv;
    float scale = (mat == 0) ? (QSCALE * LOG2E) : 1.0f;
    g_wh[idx] = __float2half(W[rem] * scale);
}

// ---------------- 1) x column-sum partials + x -> fp16 --------------------
__global__ void __launch_bounds__(256) xsum_kernel(const float* __restrict__ x)
{
    int blk = blockIdx.x;            // 0..63 : b*32 + part
    int d = threadIdx.x & 127;
    int c = threadIdx.x >> 7;        // 0..1
    int b = blk >> 5, part = blk & 31;
    size_t rbase = (size_t)b * SS + part * 128;
    const float* base = x + rbase * DD;
    __half* xb = g_xh + rbase * DD;
    float s = 0.f;
    for (int j = c; j < 128; j += 2) {
        float v = base[(size_t)j * DD + d];
        s += v;
        xb[(size_t)j * DD + d] = __float2half(v);
    }
    __shared__ float red[2][DD];
    red[c][d] = s;
    __syncthreads();
    if (c == 0)
        g_xpart[blk][d] = red[0][d] + red[1][d];
}

// ---------------- 2) vsum = W_V . xsum (fp32 exact) -----------------------
__global__ void __launch_bounds__(128) vsumw_kernel(const float* __restrict__ Wv)
{
    int bh = blockIdx.x;
    int b = bh >> 2, h = bh & 3;
    __shared__ float xs[DD];
    int tid = threadIdx.x;
    if (tid < DD) {
        float s = 0.f;
#pragma unroll
        for (int p = 0; p < 32; p++) s += g_xpart[b * 32 + p][tid];
        xs[tid] = s;
    }
    __syncthreads();
    if (tid < DH) {
        const float* Wr = Wv + (size_t)(h * DH + tid) * DD;
        float s = 0.f;
#pragma unroll 4
        for (int j = 0; j < DD; j++) s = fmaf(Wr[j], xs[j], s);
        g_vsum[bh * DH + tid] = s;
    }
}

// ---------------- 3) QKV projection via tensor cores (fp16) ---------------
__global__ void __launch_bounds__(128) projmma_kernel()
{
    int bx = blockIdx.x;
    int rowbase = blockIdx.y * 64;
    int mat = bx >> 1;
    int obase = (bx & 1) * 64;
    int tid = threadIdx.x;
    int w = tid >> 5, lane = tid & 31;
    int lrow = lane & 15, lchunk = lane >> 4;
    int r = lane >> 2, cq = lane & 3;

    __shared__ __align__(16) __half sX[64 * 128];
    __shared__ __align__(16) __half sW[64 * 128];

    const uint4* gX = (const uint4*)(g_xh + (size_t)rowbase * DD);
    const uint4* gW = (const uint4*)(g_wh + (size_t)(mat * 128 + obase) * 128);
    for (int i = tid; i < 1024; i += 128) {
        int row = i >> 4, c = i & 15;
        int off = swoff2(row, c);
        CPASYNC16(smaddr(sX + off), gX + i);
        CPASYNC16(smaddr(sW + off), gW + i);
    }
    CPCOMMIT();
    CPWAIT(0);
    __syncthreads();

    int wr = (w >> 1) * 32, wc = (w & 1) * 32;
    float acc[2][4][4];
#pragma unroll
    for (int i = 0; i < 2; i++)
#pragma unroll
        for (int j = 0; j < 4; j++)
#pragma unroll
            for (int k = 0; k < 4; k++) acc[i][j][k] = 0.f;

#pragma unroll
    for (int ks = 0; ks < 8; ks++) {
        u32 a0[4], a1[4], b0[4], b1[4];
        LDSM4(a0[0], a0[1], a0[2], a0[3], smaddr(sX + swoff2(wr + lrow,      2 * ks + lchunk)));
        LDSM4(a1[0], a1[1], a1[2], a1[3], smaddr(sX + swoff2(wr + 16 + lrow, 2 * ks + lchunk)));
        LDSM4(b0[0], b0[1], b0[2], b0[3], smaddr(sW + swoff2(wc + lrow,      2 * ks + lchunk)));
        LDSM4(b1[0], b1[1], b1[2], b1[3], smaddr(sW + swoff2(wc + 16 + lrow, 2 * ks + lchunk)));
        MMAH(acc[0][0][0], acc[0][0][1], acc[0][0][2], acc[0][0][3], a0[0], a0[1], a0[2], a0[3], b0[0], b0[2]);
        MMAH(acc[0][1][0], acc[0][1][1], acc[0][1][2], acc[0][1][3], a0[0], a0[1], a0[2], a0[3], b0[1], b0[3]);
        MMAH(acc[0][2][0], acc[0][2][1], acc[0][2][2], acc[0][2][3], a0[0], a0[1], a0[2], a0[3], b1[0], b1[2]);
        MMAH(acc[0][3][0], acc[0][3][1], acc[0][3][2], acc[0][3][3], a0[0], a0[1], a0[2], a0[3], b1[1], b1[3]);
        MMAH(acc[1][0][0], acc[1][0][1], acc[1][0][2], acc[1][0][3], a1[0], a1[1], a1[2], a1[3], b0[0], b0[2]);
        MMAH(acc[1][1][0], acc[1][1][1], acc[1][1][2], acc[1][1][3], a1[0], a1[1], a1[2], a1[3], b0[1], b0[3]);
        MMAH(acc[1][2][0], acc[1][2][1], acc[1][2][2], acc[1][2][3], a1[0], a1[1], a1[2], a1[3], b1[0], b1[2]);
        MMAH(acc[1][3][0], acc[1][3][1], acc[1][3][2], acc[1][3][3], a1[0], a1[1], a1[2], a1[3], b1[1], b1[3]);
    }

    __half* G = (mat == 0) ? g_qh : (mat == 1) ? g_kh : g_vh;
#pragma unroll
    for (int rg = 0; rg < 2; rg++) {
#pragma unroll
        for (int ng = 0; ng < 4; ng++) {
            int co = obase + wc + ng * 8 + 2 * cq;   // 0..127 within matrix
            int h = co >> 5, d = co & 31;
            int prow0 = rowbase + wr + rg * 16 + r;
            int b = prow0 >> 12, pp = prow0 & 4095;
            size_t base0 = ((size_t)((b * HH + h)) * SS + pp) * DH + d;
            u32 pk0; CVTH2(pk0, acc[rg][ng][1], acc[rg][ng][0]);
            *(u32*)(G + base0) = pk0;
            u32 pk1; CVTH2(pk1, acc[rg][ng][3], acc[rg][ng][2]);
            *(u32*)(G + base0 + (size_t)8 * DH) = pk1;
        }
    }
}

// ---------------- 4) attention core: fp16 MMA + packed ex2 ----------------
// grid (BHT, SS/128, KS), 128 threads (4 warps x 32 queries)
__global__ void __launch_bounds__(128, 3) attn_kernel()
{
    int bh = blockIdx.x;
    int qt = blockIdx.y;
    int ks = blockIdx.z;
    int tid = threadIdx.x;
    int w = tid >> 5, lane = tid & 31;
    int lrow = lane & 15, lchunk = lane >> 4;

    __shared__ __align__(16) __half sK[2][128 * 32];
    __shared__ __align__(16) __half sV[2][128 * 32];

    // ---- stage Q tile into sK[0], extract 2 A fragments ----
    {
        const uint4* gQ = (const uint4*)(g_qh + ((size_t)bh * SS + qt * 128) * DH);
        for (int i = tid; i < 512; i += 128) {
            int row = i >> 2, c = i & 3;
            *(uint4*)(sK[0] + swoff(row, c)) = gQ[i];
        }
    }
    __syncthreads();
    u32 qf0[8], qf1[8];
    {
        int row0 = w * 32 + lrow;
        LDSM4(qf0[0], qf0[1], qf0[2], qf0[3], smaddr(sK[0] + swoff(row0, lchunk)));
        LDSM4(qf0[4], qf0[5], qf0[6], qf0[7], smaddr(sK[0] + swoff(row0, 2 + lchunk)));
        int row1 = row0 + 16;
        LDSM4(qf1[0], qf1[1], qf1[2], qf1[3], smaddr(sK[0] + swoff(row1, lchunk)));
        LDSM4(qf1[4], qf1[5], qf1[6], qf1[7], smaddr(sK[0] + swoff(row1, 2 + lchunk)));
    }
    __syncthreads();   // done reading Q before cp.async overwrites sK[0]

    float oA[16], oB[16];
#pragma unroll
    for (int i = 0; i < 16; i++) { oA[i] = 0.f; oB[i] = 0.f; }
    float lA0 = 0.f, lA1 = 0.f, lB0 = 0.f, lB1 = 0.f;

    const int kbase = ks * (SS / KS);               // 1024 keys per split
    const __half* gK = g_kh + ((size_t)bh * SS + kbase) * DH;
    const __half* gV = g_vh + ((size_t)bh * SS + kbase) * DH;
    const int NCH = SS / KS / 128;                  // 8 chunks

    // prefetch chunk 0
    {
        const uint4* srcK = (const uint4*)gK;
        const uint4* srcV = (const uint4*)gV;
        for (int i = tid; i < 512; i += 128) {
            int row = i >> 2, c = i & 3;
            int off = swoff(row, c);
            CPASYNC16(smaddr(sK[0] + off), srcK + i);
            CPASYNC16(smaddr(sV[0] + off), srcV + i);
        }
        CPCOMMIT();
    }

    for (int ch = 0; ch < NCH; ch++) {
        int buf = ch & 1;
        if (ch + 1 < NCH) {
            const uint4* srcK = (const uint4*)(gK + (size_t)(ch + 1) * 128 * DH);
            const uint4* srcV = (const uint4*)(gV + (size_t)(ch + 1) * 128 * DH);
            int nb = buf ^ 1;
            for (int i = tid; i < 512; i += 128) {
                int row = i >> 2, c = i & 3;
                int off = swoff(row, c);
                CPASYNC16(smaddr(sK[nb] + off), srcK + i);
                CPASYNC16(smaddr(sV[nb] + off), srcV + i);
            }
            CPCOMMIT();
            CPWAIT(1);
        } else {
            CPWAIT(0);
        }
        __syncthreads();

        // per-chunk packed-l accumulators (f16x2; max ~17K per lane, safe)
        u32 hA0 = 0u, hA1 = 0u, hB0 = 0u, hB1 = 0u;

#pragma unroll 2
        for (int kt = 0; kt < 8; kt++) {            // 16 keys per step
            int row = kt * 16 + lrow;
            u32 k0[4], k1[4], v0[4], v1[4];
            LDSM4 (k0[0], k0[1], k0[2], k0[3], smaddr(sK[buf] + swoff(row, lchunk)));
            LDSM4 (k1[0], k1[1], k1[2], k1[3], smaddr(sK[buf] + swoff(row, 2 + lchunk)));
            LDSM4T(v0[0], v0[1], v0[2], v0[3], smaddr(sV[buf] + swoff(row, lchunk)));
            LDSM4T(v1[0], v1[1], v1[2], v1[3], smaddr(sV[buf] + swoff(row, 2 + lchunk)));

            // ---- group A (queries w*32 .. +15) ----
            {
                float sA0 = 0.f, sA1 = 0.f, sA2 = 0.f, sA3 = 0.f;
                float sB0 = 0.f, sB1 = 0.f, sB2 = 0.f, sB3 = 0.f;
                MMAH(sA0, sA1, sA2, sA3, qf0[0], qf0[1], qf0[2], qf0[3], k0[0], k0[2]);
                MMAH(sA0, sA1, sA2, sA3, qf0[4], qf0[5], qf0[6], qf0[7], k1[0], k1[2]);
                MMAH(sB0, sB1, sB2, sB3, qf0[0], qf0[1], qf0[2], qf0[3], k0[1], k0[3]);
                MMAH(sB0, sB1, sB2, sB3, qf0[4], qf0[5], qf0[6], qf0[7], k1[1], k1[3]);
                u32 p0, p1, p2, p3;
                CVTH2(p0, sA1, sA0); CVTH2(p1, sA3, sA2);
                CVTH2(p2, sB1, sB0); CVTH2(p3, sB3, sB2);
                EX2H2(p0, p0); EX2H2(p1, p1); EX2H2(p2, p2); EX2H2(p3, p3);
                HADD2(hA0, hA0, p0); HADD2(hA0, hA0, p2);   // row r
                HADD2(hA1, hA1, p1); HADD2(hA1, hA1, p3);   // row r+8
                MMAH(oA[0],  oA[1],  oA[2],  oA[3],  p0, p1, p2, p3, v0[0], v0[1]);
                MMAH(oA[4],  oA[5],  oA[6],  oA[7],  p0, p1, p2, p3, v0[2], v0[3]);
                MMAH(oA[8],  oA[9],  oA[10], oA[11], p0, p1, p2, p3, v1[0], v1[1]);
                MMAH(oA[12], oA[13], oA[14], oA[15], p0, p1, p2, p3, v1[2], v1[3]);
            }
            // ---- group B (queries w*32+16 .. +31) ----
            {
                float sA0 = 0.f, sA1 = 0.f, sA2 = 0.f, sA3 = 0.f;
                float sB0 = 0.f, sB1 = 0.f, sB2 = 0.f, sB3 = 0.f;
                MMAH(sA0, sA1, sA2, sA3, qf1[0], qf1[1], qf1[2], qf1[3], k0[0], k0[2]);
                MMAH(sA0, sA1, sA2, sA3, qf1[4], qf1[5], qf1[6], qf1[7], k1[0], k1[2]);
                MMAH(sB0, sB1, sB2, sB3, qf1[0], qf1[1], qf1[2], qf1[3], k0[1], k0[3]);
                MMAH(sB0, sB1, sB2, sB3, qf1[4], qf1[5], qf1[6], qf1[7], k1[1], k1[3]);
                u32 p0, p1, p2, p3;
                CVTH2(p0, sA1, sA0); CVTH2(p1, sA3, sA2);
                CVTH2(p2, sB1, sB0); CVTH2(p3, sB3, sB2);
                EX2H2(p0, p0); EX2H2(p1, p1); EX2H2(p2, p2); EX2H2(p3, p3);
                HADD2(hB0, hB0, p0); HADD2(hB0, hB0, p2);
                HADD2(hB1, hB1, p1); HADD2(hB1, hB1, p3);
                MMAH(oB[0],  oB[1],  oB[2],  oB[3],  p0, p1, p2, p3, v0[0], v0[1]);
                MMAH(oB[4],  oB[5],  oB[6],  oB[7],  p0, p1, p2, p3, v0[2], v0[3]);
                MMAH(oB[8],  oB[9],  oB[10], oB[11], p0, p1, p2, p3, v1[0], v1[1]);
                MMAH(oB[12], oB[13], oB[14], oB[15], p0, p1, p2, p3, v1[2], v1[3]);
            }
        }

        // flush packed-l to f32
        {
            float lo, hi;
            H2TOF2(lo, hi, hA0); lA0 += lo + hi;
            H2TOF2(lo, hi, hA1); lA1 += lo + hi;
            H2TOF2(lo, hi, hB0); lB0 += lo + hi;
            H2TOF2(lo, hi, hB1); lB1 += lo + hi;
        }
        __syncthreads();
    }

    // l reduction across row-quads
    lA0 += __shfl_xor_sync(0xffffffffu, lA0, 1);
    lA0 += __shfl_xor_sync(0xffffffffu, lA0, 2);
    lA1 += __shfl_xor_sync(0xffffffffu, lA1, 1);
    lA1 += __shfl_xor_sync(0xffffffffu, lA1, 2);
    lB0 += __shfl_xor_sync(0xffffffffu, lB0, 1);
    lB0 += __shfl_xor_sync(0xffffffffu, lB0, 2);
    lB1 += __shfl_xor_sync(0xffffffffu, lB1, 1);
    lB1 += __shfl_xor_sync(0xffffffffu, lB1, 2);

    int r = lane >> 2, cq = lane & 3;
    int qgA = qt * 128 + w * 32 + r;
    int qgB = qgA + 16;
    if (cq == 0) {
        g_lpart[((size_t)bh * SS + qgA) * KS + ks]     = lA0;
        g_lpart[((size_t)bh * SS + qgA + 8) * KS + ks] = lA1;
        g_lpart[((size_t)bh * SS + qgB) * KS + ks]     = lB0;
        g_lpart[((size_t)bh * SS + qgB + 8) * KS + ks] = lB1;
    }
#pragma unroll
    for (int d = 0; d < 4; d++) {
        u32 pk;
        CVTB2(pk, oA[d * 4 + 1], oA[d * 4 + 0]);
        *(u32*)(g_opartb + (((size_t)bh * SS + qgA) * KS + ks) * DH + d * 8 + cq * 2) = pk;
        CVTB2(pk, oA[d * 4 + 3], oA[d * 4 + 2]);
        *(u32*)(g_opartb + (((size_t)bh * SS + qgA + 8) * KS + ks) * DH + d * 8 + cq * 2) = pk;
        CVTB2(pk, oB[d * 4 + 1], oB[d * 4 + 0]);
        *(u32*)(g_opartb + (((size_t)bh * SS + qgB) * KS + ks) * DH + d * 8 + cq * 2) = pk;
        CVTB2(pk, oB[d * 4 + 3], oB[d * 4 + 2]);
        *(u32*)(g_opartb + (((size_t)bh * SS + qgB + 8) * KS + ks) * DH + d * 8 + cq * 2) = pk;
    }
}

// ---------------- 5) fused combine + output projection --------------------
__global__ void __launch_bounds__(128) outfused_kernel(
    const float* __restrict__ Wo, float* __restrict__ out)
{
    const int R = 16;
    __shared__ __align__(16) float zs[R][DD];
    __shared__ float ls[R][HH];
    int rowbase = blockIdx.x * R;
    int tid = threadIdx.x;

    // phase A: per-(row, head) inverse-l
    if (tid < R * HH) {
        int rr = tid >> 2, h = tid & 3;
        int grow = rowbase + rr;
        int b = grow >> 12, p = grow & 4095;
        int bh = b * HH + h;
        float l = 0.f;
#pragma unroll
        for (int k = 0; k < KS; k++) l += g_lpart[((size_t)bh * SS + p) * KS + k];
        ls[rr][h] = 0.5f / l;
    }
    __syncthreads();

    // phase B: build z tile
#pragma unroll
    for (int rr4 = 0; rr4 < 4; rr4++) {
        int e = rr4 * 128 + tid;          // 0..511 : 4-wide d chunk
        int row = e >> 5, fq = e & 31;
        int h = fq >> 3, dq = fq & 7;
        int grow = rowbase + row;
        int b = grow >> 12, p = grow & 4095;
        int bh = b * HH + h;
        float ox = 0.f, oy = 0.f, oz = 0.f, ow = 0.f;
#pragma unroll
        for (int k = 0; k < KS; k++) {
            uint2 t = ((const uint2*)(g_opartb + (((size_t)bh * SS + p) * KS + k) * DH))[dq];
            float2 lo = __bfloat1622float2(*(const __nv_bfloat162*)&t.x);
            float2 hi = __bfloat1622float2(*(const __nv_bfloat162*)&t.y);
            ox += lo.x; oy += lo.y; oz += hi.x; ow += hi.y;
        }
        float inv = ls[row][h];
        float4 vs = ((const float4*)(g_vsum + bh * DH))[dq];
        float4 z;
        z.x = fmaf(ox, inv, 0.5f * vs.x);
        z.y = fmaf(oy, inv, 0.5f * vs.y);
        z.z = fmaf(oz, inv, 0.5f * vs.z);
        z.w = fmaf(ow, inv, 0.5f * vs.w);
        *(float4*)(&zs[row][fq * 4]) = z;
    }
    __syncthreads();

    // phase C: out = z @ Wo^T
    const float4* Wr = (const float4*)(Wo + tid * DD);
    float acc[R];
#pragma unroll
    for (int r = 0; r < R; r++) acc[r] = 0.f;
#pragma unroll 8
    for (int jc = 0; jc < DD / 4; jc++) {
        float4 w = Wr[jc];
#pragma unroll
        for (int r = 0; r < R; r++) {
            float4 zv = *(const float4*)(&zs[r][jc * 4]);
            acc[r] = fmaf(w.x, zv.x, acc[r]);
            acc[r] = fmaf(w.y, zv.y, acc[r]);
            acc[r] = fmaf(w.z, zv.z, acc[r]);
            acc[r] = fmaf(w.w, zv.w, acc[r]);
        }
    }
#pragma unroll
    for (int r = 0; r < R; r++)
        out[(size_t)(rowbase + r) * DD + tid] = acc[r];
}

// ---------------- launch ----------------
extern "C" void kernel_launch(void* const* d_in, const int* in_sizes, int n_in,
                              void* d_out, int out_size)
{
    const float* x  = (const float*)d_in[0];
    const float* Wk = (const float*)d_in[1];
    const float* Wq = (const float*)d_in[2];
    const float* Wv = (const float*)d_in[3];
    const float* Wo = (const float*)d_in[4];
    float* out = (float*)d_out;

    wcvt_kernel<<<192, 256>>>(Wk, Wq, Wv);
    xsum_kernel<<<BB * 32, 256>>>(x);
    vsumw_kernel<<<BHT, 128>>>(Wv);
    projmma_kernel<<<dim3(6, (BB * SS) / 64), 128>>>();
    {
        dim3 grid(BHT, SS / 128, KS);
        attn_kernel<<<grid, 128>>>();
    }
    outfused_kernel<<<(BB * SS) / 16, 128>>>(Wo, out);
}